// round 5
// baseline (speedup 1.0000x reference)
#include <cuda_runtime.h>
#include <cstddef>

#define NN 50000
#define EE 800000
#define HH 256
#define AA 128
#define BB 32
#define LLAYERS 3
#define BNEPS 1e-5f

// ---------------- device scratch (allocation-free rule: module globals) ----------------
__device__ int g_deg[NN];
__device__ int g_rowcur[NN];
__device__ int g_rowptr[NN + 1];
__device__ int g_colsrc[EE];
__device__ int g_eidx[EE];
__device__ __align__(16) float g_degf[NN];
__device__ __align__(16) float g_ws[NN * BB];
__device__ __align__(16) float g_h[(size_t)NN * HH];
__device__ __align__(16) float g_h1[(size_t)NN * HH];
__device__ __align__(16) float g_feat[(size_t)NN * HH];
__device__ float g_stats[7 * 2 * HH];

// ---------------- init: zero counters + stats ----------------
__global__ void init_k() {
    int i = blockIdx.x * blockDim.x + threadIdx.x;
    int stride = gridDim.x * blockDim.x;
    for (int t = i; t < NN; t += stride) { g_deg[t] = 0; g_rowcur[t] = 0; }
    for (int t = i; t < 7 * 2 * HH; t += stride) g_stats[t] = 0.f;
}

// ---------------- degree histogram ----------------
__global__ void hist_k(const int* __restrict__ dst) {
    int e = blockIdx.x * blockDim.x + threadIdx.x;
    if (e < EE) atomicAdd(&g_deg[dst[e]], 1);
}

// ---------------- single-block exclusive scan over N=50000 + degf ----------------
__global__ void scan_k() {
    __shared__ int part[1024];
    const int t = threadIdx.x;
    const int CH = (NN + 1023) / 1024;  // 49
    const int base = t * CH;
    int s = 0;
    for (int i = 0; i < CH; i++) {
        int idx = base + i;
        if (idx < NN) s += g_deg[idx];
    }
    part[t] = s;
    __syncthreads();
    for (int off = 1; off < 1024; off <<= 1) {
        int v = (t >= off) ? part[t - off] : 0;
        __syncthreads();
        part[t] += v;
        __syncthreads();
    }
    int run = (t == 0) ? 0 : part[t - 1];
    for (int i = 0; i < CH; i++) {
        int idx = base + i;
        if (idx < NN) {
            int d = g_deg[idx];
            g_rowptr[idx] = run;
            g_degf[idx] = (float)d;
            run += d;
        }
    }
    if (t == 1023) g_rowptr[NN] = part[1023];  // == EE
}

// ---------------- CSR scatter (edges grouped by dst) ----------------
__global__ void scatter_k(const int* __restrict__ src, const int* __restrict__ dst) {
    int e = blockIdx.x * blockDim.x + threadIdx.x;
    if (e < EE) {
        int d = dst[e];
        int p = g_rowptr[d] + atomicAdd(&g_rowcur[d], 1);
        g_colsrc[p] = src[e];
        g_eidx[p] = e;
    }
}

// ---------------- ws[v] = sum over in-edges of w[e]  ([N,32]) ----------------
__global__ void ws_k(const float* __restrict__ w) {
    int gw = (blockIdx.x * blockDim.x + threadIdx.x) >> 5;
    int lane = threadIdx.x & 31;
    if (gw >= NN) return;
    int s = g_rowptr[gw], e = g_rowptr[gw + 1];
    float acc = 0.f;
    for (int j = s; j < e; j++)
        acc += __ldg(&w[(size_t)g_eidx[j] * BB + lane]);
    g_ws[(size_t)gw * BB + lane] = acc;
}

// ---------------- SpMM: O[v] = sum_{e: dst=v} F[src[e]]  (warp per node) ----------------
__global__ void spmm_k(const float* __restrict__ F, float* __restrict__ O) {
    int gw = (blockIdx.x * blockDim.x + threadIdx.x) >> 5;
    int lane = threadIdx.x & 31;
    if (gw >= NN) return;
    int s = g_rowptr[gw], e = g_rowptr[gw + 1];
    float4 a0 = make_float4(0.f, 0.f, 0.f, 0.f);
    float4 a1 = make_float4(0.f, 0.f, 0.f, 0.f);
    for (int j = s; j < e; j++) {
        const float4* r = reinterpret_cast<const float4*>(F + (size_t)g_colsrc[j] * HH);
        float4 v0 = __ldg(&r[lane]);
        float4 v1 = __ldg(&r[lane + 32]);
        a0.x += v0.x; a0.y += v0.y; a0.z += v0.z; a0.w += v0.w;
        a1.x += v1.x; a1.y += v1.y; a1.z += v1.z; a1.w += v1.w;
    }
    float4* o = reinterpret_cast<float4*>(O + (size_t)gw * HH);
    o[lane] = a0;
    o[lane + 32] = a1;
}

// ---------------- fused GEMM: C = relu(A1@W1 + A2@W2 + bias1 + deg*bias2 + addend) ----------------
// 128x128 tile, BK=8, 256 threads, 8x8 per-thread microtile.
__global__ void __launch_bounds__(256, 2) gemm_k(
    const float* __restrict__ A1, const float* __restrict__ W1, int K1,
    const float* __restrict__ A2, const float* __restrict__ W2, int K2,
    const float* __restrict__ bias1, const float* __restrict__ bias2,
    const float* __restrict__ degf, const float* __restrict__ addend,
    float* __restrict__ C)
{
    __shared__ float As[8][128];
    __shared__ float Bs[8][128];
    const int tid = threadIdx.x;
    const int tR = tid >> 4;   // 0..15
    const int tC = tid & 15;   // 0..15
    const int rowBase = blockIdx.y * 128;
    const int colBase = blockIdx.x * 128;
    const int aRow = tid >> 1;
    const int aCol = (tid & 1) << 2;
    const int bRow = tid >> 5;
    const int bCol = (tid & 31) << 2;

    float acc[8][8];
#pragma unroll
    for (int i = 0; i < 8; i++)
#pragma unroll
        for (int j = 0; j < 8; j++) acc[i][j] = 0.f;

#pragma unroll 1
    for (int part = 0; part < 2; part++) {
        const float* Ap = part ? A2 : A1;
        const float* Wp = part ? W2 : W1;
        const int K = part ? K2 : K1;
        if (Ap == nullptr) continue;
#pragma unroll 1
        for (int k0 = 0; k0 < K; k0 += 8) {
            int ar = rowBase + aRow;
            float4 av = make_float4(0.f, 0.f, 0.f, 0.f);
            if (ar < NN) av = *reinterpret_cast<const float4*>(Ap + (size_t)ar * K + k0 + aCol);
            As[aCol + 0][aRow] = av.x;
            As[aCol + 1][aRow] = av.y;
            As[aCol + 2][aRow] = av.z;
            As[aCol + 3][aRow] = av.w;
            float4 bv = *reinterpret_cast<const float4*>(Wp + (size_t)(k0 + bRow) * HH + colBase + bCol);
            *reinterpret_cast<float4*>(&Bs[bRow][bCol]) = bv;
            __syncthreads();
#pragma unroll
            for (int k = 0; k < 8; k++) {
                float ra[8], rb[8];
#pragma unroll
                for (int i = 0; i < 8; i++) ra[i] = As[k][tR * 8 + i];
#pragma unroll
                for (int j = 0; j < 8; j++) rb[j] = Bs[k][tC * 8 + j];
#pragma unroll
                for (int i = 0; i < 8; i++)
#pragma unroll
                    for (int j = 0; j < 8; j++)
                        acc[i][j] = fmaf(ra[i], rb[j], acc[i][j]);
            }
            __syncthreads();
        }
    }

#pragma unroll
    for (int i = 0; i < 8; i++) {
        int r = rowBase + tR * 8 + i;
        if (r < NN) {
            float dg = bias2 ? degf[r] : 0.f;
#pragma unroll
            for (int j = 0; j < 8; j++) {
                int c = colBase + tC * 8 + j;
                float v = acc[i][j] + bias1[c];
                if (bias2) v = fmaf(dg, bias2[c], v);
                if (addend) v += addend[(size_t)r * HH + c];
                v = fmaxf(v, 0.f);
                C[(size_t)r * HH + c] = v;
            }
        }
    }
}

// ---------------- BN stats: column sum & sumsq into st[0..H), st[H..2H) ----------------
__global__ void stats_k(const float* __restrict__ X, float* __restrict__ st) {
    int c = threadIdx.x;        // 256
    int r0 = blockIdx.x * 128;
    float s = 0.f, q = 0.f;
    for (int i = 0; i < 128; i++) {
        int r = r0 + i;
        if (r < NN) {
            float v = X[(size_t)r * HH + c];
            s += v;
            q = fmaf(v, v, q);
        }
    }
    atomicAdd(&st[c], s);
    atomicAdd(&st[HH + c], q);
}

// ---------------- BN affine apply ----------------
__global__ void bn_k(const float* __restrict__ X, float* __restrict__ Y,
                     const float* __restrict__ st, const float* __restrict__ ga,
                     const float* __restrict__ be) {
    const int c = threadIdx.x;  // 256 threads; stride multiple of 256 keeps column fixed
    const float invN = 1.0f / (float)NN;
    float mu = st[c] * invN;
    float var = st[HH + c] * invN - mu * mu;
    float sc = rsqrtf(var + BNEPS) * ga[c];
    float sh = be[c] - mu * sc;
    size_t stride = (size_t)gridDim.x * blockDim.x;
    for (size_t i = (size_t)blockIdx.x * blockDim.x + threadIdx.x; i < (size_t)NN * HH; i += stride)
        Y[i] = fmaf(X[i], sc, sh);
}

// ---------------- launcher ----------------
extern "C" void kernel_launch(void* const* d_in, const int* in_sizes, int n_in,
                              void* d_out, int out_size) {
    (void)in_sizes; (void)n_in; (void)out_size;
    const float* x      = (const float*)d_in[0];
    const float* w      = (const float*)d_in[1];
    const int*   src    = (const int*)d_in[2];
    const int*   dst    = (const int*)d_in[3];
    const float* aW     = (const float*)d_in[4];
    const float* ab     = (const float*)d_in[5];
    const float* bW0    = (const float*)d_in[6];
    const float* bb0    = (const float*)d_in[7];
    const float* gamma0 = (const float*)d_in[8];
    const float* beta0  = (const float*)d_in[9];
    const float* bondW  = (const float*)d_in[10];
    const float* bondb  = (const float*)d_in[11];
    const float* W1     = (const float*)d_in[12];
    const float* b1     = (const float*)d_in[13];
    const float* W2     = (const float*)d_in[14];
    const float* b2     = (const float*)d_in[15];
    const float* gamma1 = (const float*)d_in[16];
    const float* beta1  = (const float*)d_in[17];
    const float* gamma2 = (const float*)d_in[18];
    const float* beta2  = (const float*)d_in[19];

    float *p_degf, *p_ws, *p_h, *p_h1, *p_feat, *p_stats;
    cudaGetSymbolAddress((void**)&p_degf, g_degf);
    cudaGetSymbolAddress((void**)&p_ws, g_ws);
    cudaGetSymbolAddress((void**)&p_h, g_h);
    cudaGetSymbolAddress((void**)&p_h1, g_h1);
    cudaGetSymbolAddress((void**)&p_feat, g_feat);
    cudaGetSymbolAddress((void**)&p_stats, g_stats);

    const int EB = (EE + 255) / 256;          // 3125
    const int WB = (NN * 32 + 255) / 256;     // 6250 (warp-per-node kernels)
    const dim3 gg(HH / 128, (NN + 127) / 128);  // (2, 391)
    const int SB = (NN + 127) / 128;          // 391

    init_k<<<256, 256>>>();
    hist_k<<<EB, 256>>>(dst);
    scan_k<<<1, 1024>>>();
    scatter_k<<<EB, 256>>>(src, dst);
    ws_k<<<WB, 256>>>(w);

    // ---- first layer: h = relu(x@aW + ws@bW0 + ab + deg*bb0); feat = BN(h) ----
    gemm_k<<<gg, 256>>>(x, aW, AA, p_ws, bW0, BB, ab, bb0, p_degf, nullptr, p_h);
    stats_k<<<SB, 256>>>(p_h, p_stats);
    bn_k<<<4096, 256>>>(p_h, p_feat, p_stats, gamma0, beta0);

    // ---- message-passing layers ----
    for (int l = 0; l < LLAYERS; l++) {
        spmm_k<<<WB, 256>>>(p_feat, p_h1);
        // h = relu(h1@W1 + ws@bondW + b1 + deg*bondb)
        gemm_k<<<gg, 256>>>(p_h1, W1 + (size_t)l * HH * HH, HH,
                            p_ws, bondW + (size_t)l * BB * HH, BB,
                            b1 + l * HH, bondb + l * HH, p_degf, nullptr, p_h);
        float* st1 = p_stats + (1 + 2 * l) * 2 * HH;
        stats_k<<<SB, 256>>>(p_h, st1);
        bn_k<<<4096, 256>>>(p_h, p_h, st1, gamma1 + l * HH, beta1 + l * HH);
        // f2 = relu(h@W2 + b2 + feat)
        gemm_k<<<gg, 256>>>(p_h, W2 + (size_t)l * HH * HH, HH,
                            nullptr, nullptr, 0,
                            b2 + l * HH, nullptr, nullptr, p_feat, p_h1);
        float* st2 = p_stats + (2 + 2 * l) * 2 * HH;
        stats_k<<<SB, 256>>>(p_h1, st2);
        float* outp = (l == LLAYERS - 1) ? (float*)d_out : p_feat;
        bn_k<<<4096, 256>>>(p_h1, outp, st2, gamma2 + l * HH, beta2 + l * HH);
    }
}

// round 6
// speedup vs baseline: 2.0145x; 2.0145x over previous
#include <cuda_runtime.h>
#include <cstddef>
#include <cstdint>

#define NN 50000
#define EE 800000
#define HH 256
#define AA 128
#define BB 32
#define LLAYERS 3
#define BNEPS 1e-5f

// ---------------- device scratch ----------------
__device__ int g_deg[NN];
__device__ int g_rowcur[NN];
__device__ int g_rowptr[NN + 1];
__device__ int g_colsrc[EE];
__device__ int g_eidx[EE];
__device__ __align__(16) float g_degf[NN];
__device__ __align__(16) float g_ws[NN * BB];
__device__ __align__(16) float g_h[(size_t)NN * HH];     // Z: mid h
__device__ __align__(16) float g_h1[(size_t)NN * HH];    // Y
__device__ __align__(16) float g_feat[(size_t)NN * HH];  // X
__device__ float g_stats[7 * 2 * HH];
__device__ float g_sc[7 * HH];
__device__ float g_sh[7 * HH];

// ---------------- init ----------------
__global__ void init_k() {
    int i = blockIdx.x * blockDim.x + threadIdx.x;
    int stride = gridDim.x * blockDim.x;
    for (int t = i; t < NN; t += stride) { g_deg[t] = 0; g_rowcur[t] = 0; }
    for (int t = i; t < 7 * 2 * HH; t += stride) g_stats[t] = 0.f;
}

__global__ void hist_k(const int* __restrict__ dst) {
    int e = blockIdx.x * blockDim.x + threadIdx.x;
    if (e < EE) atomicAdd(&g_deg[dst[e]], 1);
}

__global__ void scan_k() {
    __shared__ int part[1024];
    const int t = threadIdx.x;
    const int CH = (NN + 1023) / 1024;
    const int base = t * CH;
    int s = 0;
    for (int i = 0; i < CH; i++) {
        int idx = base + i;
        if (idx < NN) s += g_deg[idx];
    }
    part[t] = s;
    __syncthreads();
    for (int off = 1; off < 1024; off <<= 1) {
        int v = (t >= off) ? part[t - off] : 0;
        __syncthreads();
        part[t] += v;
        __syncthreads();
    }
    int run = (t == 0) ? 0 : part[t - 1];
    for (int i = 0; i < CH; i++) {
        int idx = base + i;
        if (idx < NN) {
            int d = g_deg[idx];
            g_rowptr[idx] = run;
            g_degf[idx] = (float)d;
            run += d;
        }
    }
    if (t == 1023) g_rowptr[NN] = part[1023];
}

__global__ void scatter_k(const int* __restrict__ src, const int* __restrict__ dst) {
    int e = blockIdx.x * blockDim.x + threadIdx.x;
    if (e < EE) {
        int d = dst[e];
        int p = g_rowptr[d] + atomicAdd(&g_rowcur[d], 1);
        g_colsrc[p] = src[e];
        g_eidx[p] = e;
    }
}

__global__ void ws_k(const float* __restrict__ w) {
    int gw = (blockIdx.x * blockDim.x + threadIdx.x) >> 5;
    int lane = threadIdx.x & 31;
    if (gw >= NN) return;
    int s = g_rowptr[gw], e = g_rowptr[gw + 1];
    float acc = 0.f;
    for (int j = s; j < e; j++)
        acc += __ldg(&w[(size_t)g_eidx[j] * BB + lane]);
    g_ws[(size_t)gw * BB + lane] = acc;
}

// ---------------- SpMM with fused BN-affine epilogue ----------------
// O[v,c] = sc[c] * sum_{e: dst=v} F[src[e], c] + deg[v] * sh[c]
__global__ void spmm_k(const float* __restrict__ F, float* __restrict__ O,
                       const float* __restrict__ sc, const float* __restrict__ sh) {
    int gw = (blockIdx.x * blockDim.x + threadIdx.x) >> 5;
    int lane = threadIdx.x & 31;
    if (gw >= NN) return;
    int s = g_rowptr[gw], e = g_rowptr[gw + 1];
    float4 a0 = make_float4(0.f, 0.f, 0.f, 0.f);
    float4 a1 = make_float4(0.f, 0.f, 0.f, 0.f);
    for (int j = s; j < e; j++) {
        const float4* r = reinterpret_cast<const float4*>(F + (size_t)g_colsrc[j] * HH);
        float4 v0 = __ldg(&r[lane]);
        float4 v1 = __ldg(&r[lane + 32]);
        a0.x += v0.x; a0.y += v0.y; a0.z += v0.z; a0.w += v0.w;
        a1.x += v1.x; a1.y += v1.y; a1.z += v1.z; a1.w += v1.w;
    }
    float dg = (float)(e - s);
    float4 s0 = *reinterpret_cast<const float4*>(sc + lane * 4);
    float4 s1 = *reinterpret_cast<const float4*>(sc + (lane + 32) * 4);
    float4 t0 = *reinterpret_cast<const float4*>(sh + lane * 4);
    float4 t1 = *reinterpret_cast<const float4*>(sh + (lane + 32) * 4);
    float4 o0, o1;
    o0.x = fmaf(a0.x, s0.x, dg * t0.x); o0.y = fmaf(a0.y, s0.y, dg * t0.y);
    o0.z = fmaf(a0.z, s0.z, dg * t0.z); o0.w = fmaf(a0.w, s0.w, dg * t0.w);
    o1.x = fmaf(a1.x, s1.x, dg * t1.x); o1.y = fmaf(a1.y, s1.y, dg * t1.y);
    o1.z = fmaf(a1.z, s1.z, dg * t1.z); o1.w = fmaf(a1.w, s1.w, dg * t1.w);
    float4* o = reinterpret_cast<float4*>(O + (size_t)gw * HH);
    o[lane] = o0;
    o[lane + 32] = o1;
}

// ---------------- tf32 tensor-core GEMM ----------------
__device__ __forceinline__ void cpasync16(float* dst, const float* src, bool p) {
    uint32_t d = (uint32_t)__cvta_generic_to_shared(dst);
    int sz = p ? 16 : 0;
    asm volatile("cp.async.ca.shared.global [%0], [%1], 16, %2;" :: "r"(d), "l"(src), "r"(sz));
}
__device__ __forceinline__ uint32_t f2tf(float f) {
    uint32_t u;
    asm("cvt.rna.tf32.f32 %0, %1;" : "=r"(u) : "f"(f));
    return u;
}
__device__ __forceinline__ void mma8(float* d, const uint32_t* a, uint32_t b0, uint32_t b1) {
    asm volatile(
        "mma.sync.aligned.m16n8k8.row.col.f32.tf32.tf32.f32 "
        "{%0,%1,%2,%3}, {%4,%5,%6,%7}, {%8,%9}, {%0,%1,%2,%3};"
        : "+f"(d[0]), "+f"(d[1]), "+f"(d[2]), "+f"(d[3])
        : "r"(a[0]), "r"(a[1]), "r"(a[2]), "r"(a[3]), "r"(b0), "r"(b1));
}

// C = relu(A1@W1 + A2@W2 + bias1 + deg*bias2 + (addraw*asc+ash))
// Block tile 128x128, BK=16, 256 threads (8 warps, 4x2 warp grid, 32x64 warp tile).
__global__ void __launch_bounds__(256, 2) gemm_tc(
    const float* __restrict__ A1, const float* __restrict__ W1, int K1,
    const float* __restrict__ A2, const float* __restrict__ W2, int K2,
    const float* __restrict__ bias1, const float* __restrict__ bias2,
    const float* __restrict__ degf,
    const float* __restrict__ addraw, const float* __restrict__ asc,
    const float* __restrict__ ash,
    float* __restrict__ C)
{
    __shared__ float As[2][128][20];   // [m][k], pad to 20
    __shared__ float Bs[2][16][136];   // [k][n], pad to 136

    const int tid = threadIdx.x;
    const int lane = tid & 31;
    const int warp = tid >> 5;
    const int wm = (warp & 3) * 32;
    const int wn = (warp >> 2) * 64;
    const int rowBase = blockIdx.y * 128;
    const int colBase = blockIdx.x * 128;
    const int fr = lane >> 2;   // fragment row group
    const int fc = lane & 3;    // fragment col group

    float acc[2][8][4];
#pragma unroll
    for (int mt = 0; mt < 2; mt++)
#pragma unroll
        for (int nt = 0; nt < 8; nt++)
#pragma unroll
            for (int q = 0; q < 4; q++) acc[mt][nt][q] = 0.f;

    int buf = 0;
#pragma unroll 1
    for (int part = 0; part < 2; part++) {
        const float* Ap = part ? A2 : A1;
        const float* Wp = part ? W2 : W1;
        const int K = part ? K2 : K1;
        if (Ap == nullptr) continue;
        const int T = K / 16;

        // prologue: load tile 0
        {
#pragma unroll
            for (int i = 0; i < 2; i++) {
                int ch = tid + i * 256;
                int m = ch >> 2, kq = (ch & 3) * 4;
                int gm = rowBase + m;
                bool ok = gm < NN;
                const float* srcp = Ap + (ok ? ((size_t)gm * K + kq) : 0);
                cpasync16(&As[buf][m][kq], srcp, ok);
            }
#pragma unroll
            for (int i = 0; i < 2; i++) {
                int ch = tid + i * 256;
                int k = ch >> 5, nq = (ch & 31) * 4;
                cpasync16(&Bs[buf][k][nq], Wp + (size_t)k * HH + colBase + nq, true);
            }
            asm volatile("cp.async.commit_group;");
        }

#pragma unroll 1
        for (int it = 0; it < T; it++) {
            if (it + 1 < T) {
                int k0 = (it + 1) * 16;
                int nb = buf ^ 1;
#pragma unroll
                for (int i = 0; i < 2; i++) {
                    int ch = tid + i * 256;
                    int m = ch >> 2, kq = (ch & 3) * 4;
                    int gm = rowBase + m;
                    bool ok = gm < NN;
                    const float* srcp = Ap + (ok ? ((size_t)gm * K + k0 + kq) : 0);
                    cpasync16(&As[nb][m][kq], srcp, ok);
                }
#pragma unroll
                for (int i = 0; i < 2; i++) {
                    int ch = tid + i * 256;
                    int k = ch >> 5, nq = (ch & 31) * 4;
                    cpasync16(&Bs[nb][k][nq], Wp + (size_t)(k0 + k) * HH + colBase + nq, true);
                }
                asm volatile("cp.async.commit_group;");
                asm volatile("cp.async.wait_group 1;");
            } else {
                asm volatile("cp.async.wait_group 0;");
            }
            __syncthreads();

#pragma unroll
            for (int ks = 0; ks < 16; ks += 8) {
                uint32_t a[2][4];
#pragma unroll
                for (int mt = 0; mt < 2; mt++) {
                    int m = wm + mt * 16;
                    a[mt][0] = f2tf(As[buf][m + fr][ks + fc]);
                    a[mt][1] = f2tf(As[buf][m + 8 + fr][ks + fc]);
                    a[mt][2] = f2tf(As[buf][m + fr][ks + 4 + fc]);
                    a[mt][3] = f2tf(As[buf][m + 8 + fr][ks + 4 + fc]);
                }
#pragma unroll
                for (int nt = 0; nt < 8; nt++) {
                    uint32_t b0 = f2tf(Bs[buf][ks + fc][wn + nt * 8 + fr]);
                    uint32_t b1 = f2tf(Bs[buf][ks + 4 + fc][wn + nt * 8 + fr]);
                    mma8(acc[0][nt], a[0], b0, b1);
                    mma8(acc[1][nt], a[1], b0, b1);
                }
            }
            __syncthreads();
            buf ^= 1;
        }
    }

    // epilogue
#pragma unroll
    for (int mt = 0; mt < 2; mt++) {
        int rbase = rowBase + wm + mt * 16 + fr;
#pragma unroll
        for (int half = 0; half < 2; half++) {
            int rr = rbase + 8 * half;
            if (rr < NN) {
                float dg = bias2 ? degf[rr] : 0.f;
#pragma unroll
                for (int nt = 0; nt < 8; nt++) {
                    int cc = colBase + wn + nt * 8 + 2 * fc;
                    float v0 = acc[mt][nt][2 * half + 0] + bias1[cc];
                    float v1 = acc[mt][nt][2 * half + 1] + bias1[cc + 1];
                    if (bias2) {
                        v0 = fmaf(dg, bias2[cc], v0);
                        v1 = fmaf(dg, bias2[cc + 1], v1);
                    }
                    if (addraw) {
                        float2 ar = *reinterpret_cast<const float2*>(addraw + (size_t)rr * HH + cc);
                        v0 = fmaf(ar.x, asc[cc], v0 + ash[cc]);
                        v1 = fmaf(ar.y, asc[cc + 1], v1 + ash[cc + 1]);
                    }
                    v0 = fmaxf(v0, 0.f);
                    v1 = fmaxf(v1, 0.f);
                    *reinterpret_cast<float2*>(C + (size_t)rr * HH + cc) = make_float2(v0, v1);
                }
            }
        }
    }
}

// ---------------- BN stats ----------------
__global__ void stats_k(const float* __restrict__ X, float* __restrict__ st) {
    int c = threadIdx.x;
    int r0 = blockIdx.x * 128;
    float s = 0.f, q = 0.f;
    for (int i = 0; i < 128; i++) {
        int r = r0 + i;
        if (r < NN) {
            float v = X[(size_t)r * HH + c];
            s += v;
            q = fmaf(v, v, q);
        }
    }
    atomicAdd(&st[c], s);
    atomicAdd(&st[HH + c], q);
}

// ---------------- stats -> (scale, shift) ----------------
__global__ void scsh_k(const float* __restrict__ st, const float* __restrict__ ga,
                       const float* __restrict__ be, float* __restrict__ sc,
                       float* __restrict__ sh) {
    int c = threadIdx.x;
    const float invN = 1.0f / (float)NN;
    float mu = st[c] * invN;
    float var = st[HH + c] * invN - mu * mu;
    float s = rsqrtf(var + BNEPS) * ga[c];
    sc[c] = s;
    sh[c] = be[c] - mu * s;
}

// ---------------- affine apply ----------------
__global__ void aff_k(const float* __restrict__ X, float* __restrict__ Y,
                      const float* __restrict__ sc, const float* __restrict__ sh) {
    const int c = threadIdx.x;  // stride multiple of 256 keeps column fixed
    float s = sc[c];
    float t = sh[c];
    size_t stride = (size_t)gridDim.x * blockDim.x;
    for (size_t i = (size_t)blockIdx.x * blockDim.x + threadIdx.x; i < (size_t)NN * HH; i += stride)
        Y[i] = fmaf(X[i], s, t);
}

// ---------------- launcher ----------------
extern "C" void kernel_launch(void* const* d_in, const int* in_sizes, int n_in,
                              void* d_out, int out_size) {
    (void)in_sizes; (void)n_in; (void)out_size;
    const float* x      = (const float*)d_in[0];
    const float* w      = (const float*)d_in[1];
    const int*   src    = (const int*)d_in[2];
    const int*   dst    = (const int*)d_in[3];
    const float* aW     = (const float*)d_in[4];
    const float* ab     = (const float*)d_in[5];
    const float* bW0    = (const float*)d_in[6];
    const float* bb0    = (const float*)d_in[7];
    const float* gamma0 = (const float*)d_in[8];
    const float* beta0  = (const float*)d_in[9];
    const float* bondW  = (const float*)d_in[10];
    const float* bondb  = (const float*)d_in[11];
    const float* W1     = (const float*)d_in[12];
    const float* b1     = (const float*)d_in[13];
    const float* W2     = (const float*)d_in[14];
    const float* b2     = (const float*)d_in[15];
    const float* gamma1 = (const float*)d_in[16];
    const float* beta1  = (const float*)d_in[17];
    const float* gamma2 = (const float*)d_in[18];
    const float* beta2  = (const float*)d_in[19];

    float *p_degf, *p_ws, *p_h, *p_h1, *p_feat, *p_stats, *p_sc, *p_sh;
    cudaGetSymbolAddress((void**)&p_degf, g_degf);
    cudaGetSymbolAddress((void**)&p_ws, g_ws);
    cudaGetSymbolAddress((void**)&p_h, g_h);
    cudaGetSymbolAddress((void**)&p_h1, g_h1);
    cudaGetSymbolAddress((void**)&p_feat, g_feat);
    cudaGetSymbolAddress((void**)&p_stats, g_stats);
    cudaGetSymbolAddress((void**)&p_sc, g_sc);
    cudaGetSymbolAddress((void**)&p_sh, g_sh);

    const int EB = (EE + 255) / 256;
    const int WB = (NN * 32 + 255) / 256;
    const dim3 gg(HH / 128, (NN + 127) / 128);  // (2, 391)
    const int SB = (NN + 127) / 128;

    init_k<<<256, 256>>>();
    hist_k<<<EB, 256>>>(dst);
    scan_k<<<1, 1024>>>();
    scatter_k<<<EB, 256>>>(src, dst);
    ws_k<<<WB, 256>>>(w);

    // X = g_feat (prev raw), Y = g_h1, Z = g_h
    float* X = p_feat;
    float* Y = p_h1;
    float* Z = p_h;

    // ---- first layer: X = relu(x@aW + ws@bW0 + ab + deg*bb0); stats->(sc0,sh0) ----
    gemm_tc<<<gg, 256>>>(x, aW, AA, p_ws, bW0, BB, ab, bb0, p_degf,
                         nullptr, nullptr, nullptr, X);
    stats_k<<<SB, 256>>>(X, p_stats);
    scsh_k<<<1, 256>>>(p_stats, gamma0, beta0, p_sc, p_sh);
    int pidx = 0;

    for (int l = 0; l < LLAYERS; l++) {
        int midx = 1 + 2 * l;
        int oidx = 2 + 2 * l;
        // Y = sc_p * seg(X[src]) + deg * sh_p
        spmm_k<<<WB, 256>>>(X, Y, p_sc + pidx * HH, p_sh + pidx * HH);
        // Z = relu(Y@W1 + ws@bondW + b1 + deg*bondb)
        gemm_tc<<<gg, 256>>>(Y, W1 + (size_t)l * HH * HH, HH,
                             p_ws, bondW + (size_t)l * BB * HH, BB,
                             b1 + l * HH, bondb + l * HH, p_degf,
                             nullptr, nullptr, nullptr, Z);
        stats_k<<<SB, 256>>>(Z, p_stats + midx * 2 * HH);
        scsh_k<<<1, 256>>>(p_stats + midx * 2 * HH, gamma1 + l * HH, beta1 + l * HH,
                           p_sc + midx * HH, p_sh + midx * HH);
        aff_k<<<4096, 256>>>(Z, Z, p_sc + midx * HH, p_sh + midx * HH);
        // Y = relu(Z@W2 + b2 + (X*sc_p + sh_p))
        gemm_tc<<<gg, 256>>>(Z, W2 + (size_t)l * HH * HH, HH,
                             nullptr, nullptr, 0,
                             b2 + l * HH, nullptr, nullptr,
                             X, p_sc + pidx * HH, p_sh + pidx * HH, Y);
        stats_k<<<SB, 256>>>(Y, p_stats + oidx * 2 * HH);
        scsh_k<<<1, 256>>>(p_stats + oidx * 2 * HH, gamma2 + l * HH, beta2 + l * HH,
                           p_sc + oidx * HH, p_sh + oidx * HH);
        // swap X <-> Y; new prev affine = oidx
        float* tmp = X; X = Y; Y = tmp;
        pidx = oidx;
    }

    // final: out = X*sc_last + sh_last
    aff_k<<<4096, 256>>>(X, (float*)d_out, p_sc + pidx * HH, p_sh + pidx * HH);
}

// round 10
// speedup vs baseline: 2.0605x; 1.0228x over previous
#include <cuda_runtime.h>
#include <cstddef>
#include <cstdint>

#define NN 50000
#define EE 800000
#define HH 256
#define AA 128
#define BB 32
#define LLAYERS 3
#define BNEPS 1e-5f

// ---------------- device scratch ----------------
__device__ int g_deg[NN];
__device__ int g_rowcur[NN];
__device__ int g_rowptr[NN + 1];
__device__ int g_colsrc[EE];
__device__ int g_eidx[EE];
__device__ __align__(16) float g_degf[NN];
__device__ __align__(16) float g_ws[NN * BB];
__device__ __align__(16) float g_h[(size_t)NN * HH];     // Z raw
__device__ __align__(16) float g_zr[(size_t)NN * HH];    // BN(Z) rounded
__device__ __align__(16) float g_h1[(size_t)NN * HH];    // Y
__device__ __align__(16) float g_feat[(size_t)NN * HH];  // X
__device__ __align__(16) float g_xr[(size_t)NN * AA];
__device__ __align__(16) float g_aWr[AA * HH];
__device__ __align__(16) float g_bW0r[BB * HH];
__device__ __align__(16) float g_bondWr[LLAYERS * BB * HH];
__device__ __align__(16) float g_W1r[LLAYERS * HH * HH];
__device__ __align__(16) float g_W2r[LLAYERS * HH * HH];
__device__ float g_stats[7 * 2 * HH];
__device__ float g_sc[7 * HH];
__device__ float g_sh[7 * HH];

__device__ __forceinline__ float tf32r(float f) {
    uint32_t u;
    asm("cvt.rna.tf32.f32 %0, %1;" : "=r"(u) : "f"(f));
    return __uint_as_float(u);
}

// ---------------- init ----------------
__global__ void init_k() {
    int i = blockIdx.x * blockDim.x + threadIdx.x;
    int stride = gridDim.x * blockDim.x;
    for (int t = i; t < NN; t += stride) { g_deg[t] = 0; g_rowcur[t] = 0; }
    for (int t = i; t < 7 * 2 * HH; t += stride) g_stats[t] = 0.f;
}

__global__ void hist_k(const int* __restrict__ dst) {
    int e = blockIdx.x * blockDim.x + threadIdx.x;
    if (e < EE) atomicAdd(&g_deg[dst[e]], 1);
}

__global__ void scan_k() {
    __shared__ int part[1024];
    const int t = threadIdx.x;
    const int CH = (NN + 1023) / 1024;
    const int base = t * CH;
    int s = 0;
    for (int i = 0; i < CH; i++) {
        int idx = base + i;
        if (idx < NN) s += g_deg[idx];
    }
    part[t] = s;
    __syncthreads();
    for (int off = 1; off < 1024; off <<= 1) {
        int v = (t >= off) ? part[t - off] : 0;
        __syncthreads();
        part[t] += v;
        __syncthreads();
    }
    int run = (t == 0) ? 0 : part[t - 1];
    for (int i = 0; i < CH; i++) {
        int idx = base + i;
        if (idx < NN) {
            int d = g_deg[idx];
            g_rowptr[idx] = run;
            g_degf[idx] = (float)d;
            run += d;
        }
    }
    if (t == 1023) g_rowptr[NN] = part[1023];
}

__global__ void scatter_k(const int* __restrict__ src, const int* __restrict__ dst) {
    int e = blockIdx.x * blockDim.x + threadIdx.x;
    if (e < EE) {
        int d = dst[e];
        int p = g_rowptr[d] + atomicAdd(&g_rowcur[d], 1);
        g_colsrc[p] = src[e];
        g_eidx[p] = e;
    }
}

// ws = seg(w), pre-rounded to tf32
__global__ void ws_k(const float* __restrict__ w) {
    int gw = (blockIdx.x * blockDim.x + threadIdx.x) >> 5;
    int lane = threadIdx.x & 31;
    if (gw >= NN) return;
    int s = g_rowptr[gw], e = g_rowptr[gw + 1];
    float acc = 0.f;
    for (int j = s; j < e; j++)
        acc += __ldg(&w[(size_t)g_eidx[j] * BB + lane]);
    g_ws[(size_t)gw * BB + lane] = tf32r(acc);
}

// ---------------- elementwise tf32 pre-round ----------------
__global__ void preround_k(const float* __restrict__ in, float* __restrict__ out, int n) {
    int i = blockIdx.x * blockDim.x + threadIdx.x;
    if (i < n) out[i] = tf32r(in[i]);
}

// ---------------- SpMM with fused BN-affine epilogue, tf32-rounded output ----------------
// O[v,c] = tf32r( sc[c] * sum_{e: dst=v} F[src[e], c] + deg[v] * sh[c] )
__global__ void spmm_k(const float* __restrict__ F, float* __restrict__ O,
                       const float* __restrict__ sc, const float* __restrict__ sh) {
    int gw = (blockIdx.x * blockDim.x + threadIdx.x) >> 5;
    int lane = threadIdx.x & 31;
    if (gw >= NN) return;
    int s = g_rowptr[gw], e = g_rowptr[gw + 1];
    float4 a0 = make_float4(0.f, 0.f, 0.f, 0.f);
    float4 a1 = make_float4(0.f, 0.f, 0.f, 0.f);
    for (int j = s; j < e; j++) {
        const float4* r = reinterpret_cast<const float4*>(F + (size_t)g_colsrc[j] * HH);
        float4 v0 = __ldg(&r[lane]);
        float4 v1 = __ldg(&r[lane + 32]);
        a0.x += v0.x; a0.y += v0.y; a0.z += v0.z; a0.w += v0.w;
        a1.x += v1.x; a1.y += v1.y; a1.z += v1.z; a1.w += v1.w;
    }
    float dg = (float)(e - s);
    float4 s0 = *reinterpret_cast<const float4*>(sc + lane * 4);
    float4 s1 = *reinterpret_cast<const float4*>(sc + (lane + 32) * 4);
    float4 t0 = *reinterpret_cast<const float4*>(sh + lane * 4);
    float4 t1 = *reinterpret_cast<const float4*>(sh + (lane + 32) * 4);
    float4 o0, o1;
    o0.x = tf32r(fmaf(a0.x, s0.x, dg * t0.x)); o0.y = tf32r(fmaf(a0.y, s0.y, dg * t0.y));
    o0.z = tf32r(fmaf(a0.z, s0.z, dg * t0.z)); o0.w = tf32r(fmaf(a0.w, s0.w, dg * t0.w));
    o1.x = tf32r(fmaf(a1.x, s1.x, dg * t1.x)); o1.y = tf32r(fmaf(a1.y, s1.y, dg * t1.y));
    o1.z = tf32r(fmaf(a1.z, s1.z, dg * t1.z)); o1.w = tf32r(fmaf(a1.w, s1.w, dg * t1.w));
    float4* o = reinterpret_cast<float4*>(O + (size_t)gw * HH);
    o[lane] = o0;
    o[lane + 32] = o1;
}

// ---------------- tf32 tensor-core GEMM (operands pre-rounded; no in-loop cvt) ----------------
__device__ __forceinline__ void cpasync16(float* dst, const float* src, bool p) {
    uint32_t d = (uint32_t)__cvta_generic_to_shared(dst);
    int sz = p ? 16 : 0;
    asm volatile("cp.async.ca.shared.global [%0], [%1], 16, %2;" :: "r"(d), "l"(src), "r"(sz));
}
__device__ __forceinline__ void mma8(float* d, const uint32_t* a, uint32_t b0, uint32_t b1) {
    asm volatile(
        "mma.sync.aligned.m16n8k8.row.col.f32.tf32.tf32.f32 "
        "{%0,%1,%2,%3}, {%4,%5,%6,%7}, {%8,%9}, {%0,%1,%2,%3};"
        : "+f"(d[0]), "+f"(d[1]), "+f"(d[2]), "+f"(d[3])
        : "r"(a[0]), "r"(a[1]), "r"(a[2]), "r"(a[3]), "r"(b0), "r"(b1));
}

// C = relu(A1@W1 + A2@W2 + bias1 + deg*bias2 + (addraw*asc+ash)), fused column stats.
__global__ void __launch_bounds__(256, 2) gemm_tc(
    const float* __restrict__ A1, const float* __restrict__ W1, int K1,
    const float* __restrict__ A2, const float* __restrict__ W2, int K2,
    const float* __restrict__ bias1, const float* __restrict__ bias2,
    const float* __restrict__ degf,
    const float* __restrict__ addraw, const float* __restrict__ asc,
    const float* __restrict__ ash,
    float* __restrict__ stout,
    float* __restrict__ C)
{
    __shared__ float As[2][128][20];
    __shared__ float Bs[2][16][136];

    const int tid = threadIdx.x;
    const int lane = tid & 31;
    const int warp = tid >> 5;
    const int wm = (warp & 3) * 32;
    const int wn = (warp >> 2) * 64;
    const int rowBase = blockIdx.y * 128;
    const int colBase = blockIdx.x * 128;
    const int fr = lane >> 2;
    const int fc = lane & 3;

    float acc[2][8][4];
#pragma unroll
    for (int mt = 0; mt < 2; mt++)
#pragma unroll
        for (int nt = 0; nt < 8; nt++)
#pragma unroll
            for (int q = 0; q < 4; q++) acc[mt][nt][q] = 0.f;

    int buf = 0;
#pragma unroll 1
    for (int part = 0; part < 2; part++) {
        const float* Ap = part ? A2 : A1;
        const float* Wp = part ? W2 : W1;
        const int K = part ? K2 : K1;
        if (Ap == nullptr) continue;
        const int T = K / 16;

        {
#pragma unroll
            for (int i = 0; i < 2; i++) {
                int ch = tid + i * 256;
                int m = ch >> 2, kq = (ch & 3) * 4;
                int gm = rowBase + m;
                bool ok = gm < NN;
                const float* srcp = Ap + (ok ? ((size_t)gm * K + kq) : 0);
                cpasync16(&As[buf][m][kq], srcp, ok);
            }
#pragma unroll
            for (int i = 0; i < 2; i++) {
                int ch = tid + i * 256;
                int k = ch >> 5, nq = (ch & 31) * 4;
                cpasync16(&Bs[buf][k][nq], Wp + (size_t)k * HH + colBase + nq, true);
            }
            asm volatile("cp.async.commit_group;");
        }

#pragma unroll 1
        for (int it = 0; it < T; it++) {
            if (it + 1 < T) {
                int k0 = (it + 1) * 16;
                int nb = buf ^ 1;
#pragma unroll
                for (int i = 0; i < 2; i++) {
                    int ch = tid + i * 256;
                    int m = ch >> 2, kq = (ch & 3) * 4;
                    int gm = rowBase + m;
                    bool ok = gm < NN;
                    const float* srcp = Ap + (ok ? ((size_t)gm * K + k0 + kq) : 0);
                    cpasync16(&As[nb][m][kq], srcp, ok);
                }
#pragma unroll
                for (int i = 0; i < 2; i++) {
                    int ch = tid + i * 256;
                    int k = ch >> 5, nq = (ch & 31) * 4;
                    cpasync16(&Bs[nb][k][nq], Wp + (size_t)(k0 + k) * HH + colBase + nq, true);
                }
                asm volatile("cp.async.commit_group;");
                asm volatile("cp.async.wait_group 1;");
            } else {
                asm volatile("cp.async.wait_group 0;");
            }
            __syncthreads();

#pragma unroll
            for (int ks = 0; ks < 16; ks += 8) {
                uint32_t a[2][4];
#pragma unroll
                for (int mt = 0; mt < 2; mt++) {
                    int m = wm + mt * 16;
                    a[mt][0] = __float_as_uint(As[buf][m + fr][ks + fc]);
                    a[mt][1] = __float_as_uint(As[buf][m + 8 + fr][ks + fc]);
                    a[mt][2] = __float_as_uint(As[buf][m + fr][ks + 4 + fc]);
                    a[mt][3] = __float_as_uint(As[buf][m + 8 + fr][ks + 4 + fc]);
                }
#pragma unroll
                for (int nt = 0; nt < 8; nt++) {
                    uint32_t b0 = __float_as_uint(Bs[buf][ks + fc][wn + nt * 8 + fr]);
                    uint32_t b1 = __float_as_uint(Bs[buf][ks + 4 + fc][wn + nt * 8 + fr]);
                    mma8(acc[0][nt], a[0], b0, b1);
                    mma8(acc[1][nt], a[1], b0, b1);
                }
            }
            __syncthreads();
            buf ^= 1;
        }
    }

    // epilogue + fused stats
    float cs0[8], cs1[8], cq0[8], cq1[8];
#pragma unroll
    for (int nt = 0; nt < 8; nt++) { cs0[nt] = 0.f; cs1[nt] = 0.f; cq0[nt] = 0.f; cq1[nt] = 0.f; }

#pragma unroll
    for (int mt = 0; mt < 2; mt++) {
        int rbase = rowBase + wm + mt * 16 + fr;
#pragma unroll
        for (int half = 0; half < 2; half++) {
            int rr = rbase + 8 * half;
            if (rr < NN) {
                float dg = bias2 ? degf[rr] : 0.f;
#pragma unroll
                for (int nt = 0; nt < 8; nt++) {
                    int cc = colBase + wn + nt * 8 + 2 * fc;
                    float v0 = acc[mt][nt][2 * half + 0] + bias1[cc];
                    float v1 = acc[mt][nt][2 * half + 1] + bias1[cc + 1];
                    if (bias2) {
                        v0 = fmaf(dg, bias2[cc], v0);
                        v1 = fmaf(dg, bias2[cc + 1], v1);
                    }
                    if (addraw) {
                        float2 ar = *reinterpret_cast<const float2*>(addraw + (size_t)rr * HH + cc);
                        v0 = fmaf(ar.x, asc[cc], v0 + ash[cc]);
                        v1 = fmaf(ar.y, asc[cc + 1], v1 + ash[cc + 1]);
                    }
                    v0 = fmaxf(v0, 0.f);
                    v1 = fmaxf(v1, 0.f);
                    cs0[nt] += v0; cq0[nt] = fmaf(v0, v0, cq0[nt]);
                    cs1[nt] += v1; cq1[nt] = fmaf(v1, v1, cq1[nt]);
                    *reinterpret_cast<float2*>(C + (size_t)rr * HH + cc) = make_float2(v0, v1);
                }
            }
        }
    }

    if (stout) {
#pragma unroll
        for (int nt = 0; nt < 8; nt++) {
#pragma unroll
            for (int off = 4; off < 32; off <<= 1) {
                cs0[nt] += __shfl_xor_sync(0xffffffffu, cs0[nt], off);
                cs1[nt] += __shfl_xor_sync(0xffffffffu, cs1[nt], off);
                cq0[nt] += __shfl_xor_sync(0xffffffffu, cq0[nt], off);
                cq1[nt] += __shfl_xor_sync(0xffffffffu, cq1[nt], off);
            }
            if (lane < 4) {
                int cc = colBase + wn + nt * 8 + 2 * lane;
                atomicAdd(&stout[cc], cs0[nt]);
                atomicAdd(&stout[cc + 1], cs1[nt]);
                atomicAdd(&stout[HH + cc], cq0[nt]);
                atomicAdd(&stout[HH + cc + 1], cq1[nt]);
            }
        }
    }
}

// ---------------- stats -> (scale, shift) ----------------
__global__ void scsh_k(const float* __restrict__ st, const float* __restrict__ ga,
                       const float* __restrict__ be, float* __restrict__ sc,
                       float* __restrict__ sh) {
    int c = threadIdx.x;
    const float invN = 1.0f / (float)NN;
    float mu = st[c] * invN;
    float var = st[HH + c] * invN - mu * mu;
    float s = rsqrtf(var + BNEPS) * ga[c];
    sc[c] = s;
    sh[c] = be[c] - mu * s;
}

// ---------------- affine apply (doRound: tf32-round output for MMA use) ----------------
__global__ void aff_k(const float* __restrict__ X, float* __restrict__ Y,
                      const float* __restrict__ sc, const float* __restrict__ sh,
                      int doRound) {
    const int c = threadIdx.x;  // stride multiple of 256 keeps column fixed
    float s = sc[c];
    float t = sh[c];
    size_t stride = (size_t)gridDim.x * blockDim.x;
    if (doRound) {
        for (size_t i = (size_t)blockIdx.x * blockDim.x + threadIdx.x; i < (size_t)NN * HH; i += stride)
            Y[i] = tf32r(fmaf(X[i], s, t));
    } else {
        for (size_t i = (size_t)blockIdx.x * blockDim.x + threadIdx.x; i < (size_t)NN * HH; i += stride)
            Y[i] = fmaf(X[i], s, t);
    }
}

// ---------------- launcher ----------------
extern "C" void kernel_launch(void* const* d_in, const int* in_sizes, int n_in,
                              void* d_out, int out_size) {
    (void)in_sizes; (void)n_in; (void)out_size;
    const float* x      = (const float*)d_in[0];
    const float* w      = (const float*)d_in[1];
    const int*   src    = (const int*)d_in[2];
    const int*   dst    = (const int*)d_in[3];
    const float* aW     = (const float*)d_in[4];
    const float* ab     = (const float*)d_in[5];
    const float* bW0    = (const float*)d_in[6];
    const float* bb0    = (const float*)d_in[7];
    const float* gamma0 = (const float*)d_in[8];
    const float* beta0  = (const float*)d_in[9];
    const float* bondW  = (const float*)d_in[10];
    const float* bondb  = (const float*)d_in[11];
    const float* W1     = (const float*)d_in[12];
    const float* b1     = (const float*)d_in[13];
    const float* W2     = (const float*)d_in[14];
    const float* b2     = (const float*)d_in[15];
    const float* gamma1 = (const float*)d_in[16];
    const float* beta1  = (const float*)d_in[17];
    const float* gamma2 = (const float*)d_in[18];
    const float* beta2  = (const float*)d_in[19];

    float *p_degf, *p_ws, *p_h, *p_zr, *p_h1, *p_feat, *p_stats, *p_sc, *p_sh;
    float *p_xr, *p_aWr, *p_bW0r, *p_bondWr, *p_W1r, *p_W2r;
    cudaGetSymbolAddress((void**)&p_degf, g_degf);
    cudaGetSymbolAddress((void**)&p_ws, g_ws);
    cudaGetSymbolAddress((void**)&p_h, g_h);
    cudaGetSymbolAddress((void**)&p_zr, g_zr);
    cudaGetSymbolAddress((void**)&p_h1, g_h1);
    cudaGetSymbolAddress((void**)&p_feat, g_feat);
    cudaGetSymbolAddress((void**)&p_stats, g_stats);
    cudaGetSymbolAddress((void**)&p_sc, g_sc);
    cudaGetSymbolAddress((void**)&p_sh, g_sh);
    cudaGetSymbolAddress((void**)&p_xr, g_xr);
    cudaGetSymbolAddress((void**)&p_aWr, g_aWr);
    cudaGetSymbolAddress((void**)&p_bW0r, g_bW0r);
    cudaGetSymbolAddress((void**)&p_bondWr, g_bondWr);
    cudaGetSymbolAddress((void**)&p_W1r, g_W1r);
    cudaGetSymbolAddress((void**)&p_W2r, g_W2r);

    const int EB = (EE + 255) / 256;
    const int WB = (NN * 32 + 255) / 256;
    const dim3 gg(HH / 128, (NN + 127) / 128);  // (2, 391)

    init_k<<<256, 256>>>();
    hist_k<<<EB, 256>>>(dst);
    scan_k<<<1, 1024>>>();
    scatter_k<<<EB, 256>>>(src, dst);
    ws_k<<<WB, 256>>>(w);

    // pre-round all static MMA operands (bit-identical to R5's in-loop cvt.rna)
    preround_k<<<(NN * AA + 255) / 256, 256>>>(x, p_xr, NN * AA);
    preround_k<<<(AA * HH + 255) / 256, 256>>>(aW, p_aWr, AA * HH);
    preround_k<<<(BB * HH + 255) / 256, 256>>>(bW0, p_bW0r, BB * HH);
    preround_k<<<(LLAYERS * BB * HH + 255) / 256, 256>>>(bondW, p_bondWr, LLAYERS * BB * HH);
    preround_k<<<(LLAYERS * HH * HH + 255) / 256, 256>>>(W1, p_W1r, LLAYERS * HH * HH);
    preround_k<<<(LLAYERS * HH * HH + 255) / 256, 256>>>(W2, p_W2r, LLAYERS * HH * HH);

    float* X = p_feat;   // raw (pre-BN) layer output
    float* Y = p_h1;
    float* Z = p_h;

    // ---- first layer: X = relu(x@aW + ws@bW0 + ab + deg*bb0); fused stats0 ----
    gemm_tc<<<gg, 256>>>(p_xr, p_aWr, AA, p_ws, p_bW0r, BB, ab, bb0, p_degf,
                         nullptr, nullptr, nullptr, p_stats, X);
    scsh_k<<<1, 256>>>(p_stats, gamma0, beta0, p_sc, p_sh);
    int pidx = 0;

    for (int l = 0; l < LLAYERS; l++) {
        int midx = 1 + 2 * l;
        int oidx = 2 + 2 * l;
        const float* scp = p_sc + pidx * HH;
        const float* shp = p_sh + pidx * HH;
        // Y = tf32r(sc_p * seg(X[src]) + deg * sh_p)   (centered BEFORE rounding)
        spmm_k<<<WB, 256>>>(X, Y, scp, shp);
        // Z = relu(Y@W1 + ws@bondW + b1 + deg*bondb); fused stats mid
        gemm_tc<<<gg, 256>>>(Y, p_W1r + (size_t)l * HH * HH, HH,
                             p_ws, p_bondWr + (size_t)l * BB * HH, BB,
                             b1 + l * HH, bondb + l * HH, p_degf,
                             nullptr, nullptr, nullptr,
                             p_stats + midx * 2 * HH, Z);
        scsh_k<<<1, 256>>>(p_stats + midx * 2 * HH, gamma1 + l * HH, beta1 + l * HH,
                           p_sc + midx * HH, p_sh + midx * HH);
        // Zr = tf32r(BN(Z))  (centered BEFORE rounding)
        aff_k<<<4096, 256>>>(Z, p_zr, p_sc + midx * HH, p_sh + midx * HH, 1);
        // Y = relu(Zr@W2 + b2 + (X*sc_p + sh_p)); fused stats out
        gemm_tc<<<gg, 256>>>(p_zr, p_W2r + (size_t)l * HH * HH, HH,
                             nullptr, nullptr, 0,
                             b2 + l * HH, nullptr, nullptr,
                             X, scp, shp,
                             p_stats + oidx * 2 * HH, Y);
        scsh_k<<<1, 256>>>(p_stats + oidx * 2 * HH, gamma2 + l * HH, beta2 + l * HH,
                           p_sc + oidx * HH, p_sh + oidx * HH);
        float* tmp = X; X = Y; Y = tmp;
        pidx = oidx;
    }

    // final: out = X*sc_last + sh_last (no rounding)
    aff_k<<<4096, 256>>>(X, (float*)d_out, p_sc + pidx * HH, p_sh + pidx * HH, 0);
}

// round 11
// speedup vs baseline: 2.0781x; 1.0086x over previous
#include <cuda_runtime.h>
#include <cstddef>
#include <cstdint>

#define NN 50000
#define EE 800000
#define HH 256
#define AA 128
#define BB 32
#define LLAYERS 3
#define BNEPS 1e-5f

// ---------------- device scratch ----------------
__device__ int g_deg[NN];
__device__ int g_rowcur[NN];
__device__ int g_rowptr[NN + 1];
__device__ int g_colsrc[EE];
__device__ int g_eidx[EE];
__device__ __align__(16) float g_degf[NN];
__device__ __align__(16) float g_ws[NN * BB];
__device__ __align__(16) float g_h[(size_t)NN * HH];     // Z raw
__device__ __align__(16) float g_zr[(size_t)NN * HH];    // BN(Z) rounded
__device__ __align__(16) float g_h1[(size_t)NN * HH];    // Y
__device__ __align__(16) float g_feat[(size_t)NN * HH];  // X
__device__ __align__(16) float g_xr[(size_t)NN * AA];
__device__ __align__(16) float g_aWr[AA * HH];
__device__ __align__(16) float g_bW0r[BB * HH];
__device__ __align__(16) float g_bondWr[LLAYERS * BB * HH];
__device__ __align__(16) float g_W1r[LLAYERS * HH * HH];
__device__ __align__(16) float g_W2r[LLAYERS * HH * HH];
__device__ float g_stats[7 * 2 * HH];
__device__ float g_sc[7 * HH];
__device__ float g_sh[7 * HH];

__device__ __forceinline__ float tf32r(float f) {
    uint32_t u;
    asm("cvt.rna.tf32.f32 %0, %1;" : "=r"(u) : "f"(f));
    return __uint_as_float(u);
}

// ---------------- init ----------------
__global__ void init_k() {
    int i = blockIdx.x * blockDim.x + threadIdx.x;
    int stride = gridDim.x * blockDim.x;
    for (int t = i; t < NN; t += stride) { g_deg[t] = 0; g_rowcur[t] = 0; }
    for (int t = i; t < 7 * 2 * HH; t += stride) g_stats[t] = 0.f;
}

__global__ void hist_k(const int* __restrict__ dst) {
    int e = blockIdx.x * blockDim.x + threadIdx.x;
    if (e < EE) atomicAdd(&g_deg[dst[e]], 1);
}

__global__ void scan_k() {
    __shared__ int part[1024];
    const int t = threadIdx.x;
    const int CH = (NN + 1023) / 1024;
    const int base = t * CH;
    int s = 0;
    for (int i = 0; i < CH; i++) {
        int idx = base + i;
        if (idx < NN) s += g_deg[idx];
    }
    part[t] = s;
    __syncthreads();
    for (int off = 1; off < 1024; off <<= 1) {
        int v = (t >= off) ? part[t - off] : 0;
        __syncthreads();
        part[t] += v;
        __syncthreads();
    }
    int run = (t == 0) ? 0 : part[t - 1];
    for (int i = 0; i < CH; i++) {
        int idx = base + i;
        if (idx < NN) {
            int d = g_deg[idx];
            g_rowptr[idx] = run;
            g_degf[idx] = (float)d;
            run += d;
        }
    }
    if (t == 1023) g_rowptr[NN] = part[1023];
}

__global__ void scatter_k(const int* __restrict__ src, const int* __restrict__ dst) {
    int e = blockIdx.x * blockDim.x + threadIdx.x;
    if (e < EE) {
        int d = dst[e];
        int p = g_rowptr[d] + atomicAdd(&g_rowcur[d], 1);
        g_colsrc[p] = src[e];
        g_eidx[p] = e;
    }
}

// ws = seg(w), pre-rounded to tf32
__global__ void ws_k(const float* __restrict__ w) {
    int gw = (blockIdx.x * blockDim.x + threadIdx.x) >> 5;
    int lane = threadIdx.x & 31;
    if (gw >= NN) return;
    int s = g_rowptr[gw], e = g_rowptr[gw + 1];
    float acc = 0.f;
    for (int j = s; j < e; j++)
        acc += __ldg(&w[(size_t)g_eidx[j] * BB + lane]);
    g_ws[(size_t)gw * BB + lane] = tf32r(acc);
}

// ---------------- elementwise tf32 pre-round ----------------
__global__ void preround_k(const float* __restrict__ in, float* __restrict__ out, int n) {
    int i = blockIdx.x * blockDim.x + threadIdx.x;
    if (i < n) out[i] = tf32r(in[i]);
}

// ---------------- SpMM with fused BN-affine epilogue, tf32-rounded output ----------------
// O[v,c] = tf32r( sc[c] * sum_{e: dst=v} F[src[e], c] + deg[v] * sh[c] )
__global__ void spmm_k(const float* __restrict__ F, float* __restrict__ O,
                       const float* __restrict__ sc, const float* __restrict__ sh) {
    int gw = (blockIdx.x * blockDim.x + threadIdx.x) >> 5;
    int lane = threadIdx.x & 31;
    if (gw >= NN) return;
    int s = g_rowptr[gw], e = g_rowptr[gw + 1];
    float4 a0 = make_float4(0.f, 0.f, 0.f, 0.f);
    float4 a1 = make_float4(0.f, 0.f, 0.f, 0.f);
    for (int j = s; j < e; j++) {
        const float4* r = reinterpret_cast<const float4*>(F + (size_t)g_colsrc[j] * HH);
        float4 v0 = __ldg(&r[lane]);
        float4 v1 = __ldg(&r[lane + 32]);
        a0.x += v0.x; a0.y += v0.y; a0.z += v0.z; a0.w += v0.w;
        a1.x += v1.x; a1.y += v1.y; a1.z += v1.z; a1.w += v1.w;
    }
    float dg = (float)(e - s);
    float4 s0 = *reinterpret_cast<const float4*>(sc + lane * 4);
    float4 s1 = *reinterpret_cast<const float4*>(sc + (lane + 32) * 4);
    float4 t0 = *reinterpret_cast<const float4*>(sh + lane * 4);
    float4 t1 = *reinterpret_cast<const float4*>(sh + (lane + 32) * 4);
    float4 o0, o1;
    o0.x = tf32r(fmaf(a0.x, s0.x, dg * t0.x)); o0.y = tf32r(fmaf(a0.y, s0.y, dg * t0.y));
    o0.z = tf32r(fmaf(a0.z, s0.z, dg * t0.z)); o0.w = tf32r(fmaf(a0.w, s0.w, dg * t0.w));
    o1.x = tf32r(fmaf(a1.x, s1.x, dg * t1.x)); o1.y = tf32r(fmaf(a1.y, s1.y, dg * t1.y));
    o1.z = tf32r(fmaf(a1.z, s1.z, dg * t1.z)); o1.w = tf32r(fmaf(a1.w, s1.w, dg * t1.w));
    float4* o = reinterpret_cast<float4*>(O + (size_t)gw * HH);
    o[lane] = o0;
    o[lane + 32] = o1;
}

// ---------------- tf32 tensor-core GEMM (operands pre-rounded; no in-loop cvt) ----------------
__device__ __forceinline__ void cpasync16(float* dst, const float* src, bool p) {
    uint32_t d = (uint32_t)__cvta_generic_to_shared(dst);
    int sz = p ? 16 : 0;
    asm volatile("cp.async.ca.shared.global [%0], [%1], 16, %2;" :: "r"(d), "l"(src), "r"(sz));
}
__device__ __forceinline__ void mma8(float* d, const uint32_t* a, uint32_t b0, uint32_t b1) {
    asm volatile(
        "mma.sync.aligned.m16n8k8.row.col.f32.tf32.tf32.f32 "
        "{%0,%1,%2,%3}, {%4,%5,%6,%7}, {%8,%9}, {%0,%1,%2,%3};"
        : "+f"(d[0]), "+f"(d[1]), "+f"(d[2]), "+f"(d[3])
        : "r"(a[0]), "r"(a[1]), "r"(a[2]), "r"(a[3]), "r"(b0), "r"(b1));
}

// C = relu(A1@W1 + A2@W2 + bias1 + deg*bias2 + (addraw*asc+ash)), fused column stats.
__global__ void __launch_bounds__(256, 2) gemm_tc(
    const float* __restrict__ A1, const float* __restrict__ W1, int K1,
    const float* __restrict__ A2, const float* __restrict__ W2, int K2,
    const float* __restrict__ bias1, const float* __restrict__ bias2,
    const float* __restrict__ degf,
    const float* __restrict__ addraw, const float* __restrict__ asc,
    const float* __restrict__ ash,
    float* __restrict__ stout,
    float* __restrict__ C)
{
    __shared__ float As[2][128][20];
    __shared__ float Bs[2][16][136];

    const int tid = threadIdx.x;
    const int lane = tid & 31;
    const int warp = tid >> 5;
    const int wm = (warp & 3) * 32;
    const int wn = (warp >> 2) * 64;
    const int rowBase = blockIdx.y * 128;
    const int colBase = blockIdx.x * 128;
    const int fr = lane >> 2;
    const int fc = lane & 3;

    float acc[2][8][4];
#pragma unroll
    for (int mt = 0; mt < 2; mt++)
#pragma unroll
        for (int nt = 0; nt < 8; nt++)
#pragma unroll
            for (int q = 0; q < 4; q++) acc[mt][nt][q] = 0.f;

    int buf = 0;
#pragma unroll 1
    for (int part = 0; part < 2; part++) {
        const float* Ap = part ? A2 : A1;
        const float* Wp = part ? W2 : W1;
        const int K = part ? K2 : K1;
        if (Ap == nullptr) continue;
        const int T = K / 16;

        {
#pragma unroll
            for (int i = 0; i < 2; i++) {
                int ch = tid + i * 256;
                int m = ch >> 2, kq = (ch & 3) * 4;
                int gm = rowBase + m;
                bool ok = gm < NN;
                const float* srcp = Ap + (ok ? ((size_t)gm * K + kq) : 0);
                cpasync16(&As[buf][m][kq], srcp, ok);
            }
#pragma unroll
            for (int i = 0; i < 2; i++) {
                int ch = tid + i * 256;
                int k = ch >> 5, nq = (ch & 31) * 4;
                cpasync16(&Bs[buf][k][nq], Wp + (size_t)k * HH + colBase + nq, true);
            }
            asm volatile("cp.async.commit_group;");
        }

#pragma unroll 1
        for (int it = 0; it < T; it++) {
            if (it + 1 < T) {
                int k0 = (it + 1) * 16;
                int nb = buf ^ 1;
#pragma unroll
                for (int i = 0; i < 2; i++) {
                    int ch = tid + i * 256;
                    int m = ch >> 2, kq = (ch & 3) * 4;
                    int gm = rowBase + m;
                    bool ok = gm < NN;
                    const float* srcp = Ap + (ok ? ((size_t)gm * K + k0 + kq) : 0);
                    cpasync16(&As[nb][m][kq], srcp, ok);
                }
#pragma unroll
                for (int i = 0; i < 2; i++) {
                    int ch = tid + i * 256;
                    int k = ch >> 5, nq = (ch & 31) * 4;
                    cpasync16(&Bs[nb][k][nq], Wp + (size_t)(k0 + k) * HH + colBase + nq, true);
                }
                asm volatile("cp.async.commit_group;");
                asm volatile("cp.async.wait_group 1;");
            } else {
                asm volatile("cp.async.wait_group 0;");
            }
            __syncthreads();

#pragma unroll
            for (int ks = 0; ks < 16; ks += 8) {
                uint32_t a[2][4];
#pragma unroll
                for (int mt = 0; mt < 2; mt++) {
                    int m = wm + mt * 16;
                    a[mt][0] = __float_as_uint(As[buf][m + fr][ks + fc]);
                    a[mt][1] = __float_as_uint(As[buf][m + 8 + fr][ks + fc]);
                    a[mt][2] = __float_as_uint(As[buf][m + fr][ks + 4 + fc]);
                    a[mt][3] = __float_as_uint(As[buf][m + 8 + fr][ks + 4 + fc]);
                }
#pragma unroll
                for (int nt = 0; nt < 8; nt++) {
                    uint32_t b0 = __float_as_uint(Bs[buf][ks + fc][wn + nt * 8 + fr]);
                    uint32_t b1 = __float_as_uint(Bs[buf][ks + 4 + fc][wn + nt * 8 + fr]);
                    mma8(acc[0][nt], a[0], b0, b1);
                    mma8(acc[1][nt], a[1], b0, b1);
                }
            }
            __syncthreads();
            buf ^= 1;
        }
    }

    // epilogue + fused stats
    float cs0[8], cs1[8], cq0[8], cq1[8];
#pragma unroll
    for (int nt = 0; nt < 8; nt++) { cs0[nt] = 0.f; cs1[nt] = 0.f; cq0[nt] = 0.f; cq1[nt] = 0.f; }

#pragma unroll
    for (int mt = 0; mt < 2; mt++) {
        int rbase = rowBase + wm + mt * 16 + fr;
#pragma unroll
        for (int half = 0; half < 2; half++) {
            int rr = rbase + 8 * half;
            if (rr < NN) {
                float dg = bias2 ? degf[rr] : 0.f;
#pragma unroll
                for (int nt = 0; nt < 8; nt++) {
                    int cc = colBase + wn + nt * 8 + 2 * fc;
                    float v0 = acc[mt][nt][2 * half + 0] + bias1[cc];
                    float v1 = acc[mt][nt][2 * half + 1] + bias1[cc + 1];
                    if (bias2) {
                        v0 = fmaf(dg, bias2[cc], v0);
                        v1 = fmaf(dg, bias2[cc + 1], v1);
                    }
                    if (addraw) {
                        float2 ar = *reinterpret_cast<const float2*>(addraw + (size_t)rr * HH + cc);
                        v0 = fmaf(ar.x, asc[cc], v0 + ash[cc]);
                        v1 = fmaf(ar.y, asc[cc + 1], v1 + ash[cc + 1]);
                    }
                    v0 = fmaxf(v0, 0.f);
                    v1 = fmaxf(v1, 0.f);
                    cs0[nt] += v0; cq0[nt] = fmaf(v0, v0, cq0[nt]);
                    cs1[nt] += v1; cq1[nt] = fmaf(v1, v1, cq1[nt]);
                    *reinterpret_cast<float2*>(C + (size_t)rr * HH + cc) = make_float2(v0, v1);
                }
            }
        }
    }

    if (stout) {
#pragma unroll
        for (int nt = 0; nt < 8; nt++) {
#pragma unroll
            for (int off = 4; off < 32; off <<= 1) {
                cs0[nt] += __shfl_xor_sync(0xffffffffu, cs0[nt], off);
                cs1[nt] += __shfl_xor_sync(0xffffffffu, cs1[nt], off);
                cq0[nt] += __shfl_xor_sync(0xffffffffu, cq0[nt], off);
                cq1[nt] += __shfl_xor_sync(0xffffffffu, cq1[nt], off);
            }
            if (lane < 4) {
                int cc = colBase + wn + nt * 8 + 2 * lane;
                atomicAdd(&stout[cc], cs0[nt]);
                atomicAdd(&stout[cc + 1], cs1[nt]);
                atomicAdd(&stout[HH + cc], cq0[nt]);
                atomicAdd(&stout[HH + cc + 1], cq1[nt]);
            }
        }
    }
}

// ---------------- stats -> (scale, shift) ----------------
__global__ void scsh_k(const float* __restrict__ st, const float* __restrict__ ga,
                       const float* __restrict__ be, float* __restrict__ sc,
                       float* __restrict__ sh) {
    int c = threadIdx.x;
    const float invN = 1.0f / (float)NN;
    float mu = st[c] * invN;
    float var = st[HH + c] * invN - mu * mu;
    float s = rsqrtf(var + BNEPS) * ga[c];
    sc[c] = s;
    sh[c] = be[c] - mu * s;
}

// ---------------- affine apply (doRound: tf32-round output for MMA use) ----------------
__global__ void aff_k(const float* __restrict__ X, float* __restrict__ Y,
                      const float* __restrict__ sc, const float* __restrict__ sh,
                      int doRound) {
    const int c = threadIdx.x;  // stride multiple of 256 keeps column fixed
    float s = sc[c];
    float t = sh[c];
    size_t stride = (size_t)gridDim.x * blockDim.x;
    if (doRound) {
        for (size_t i = (size_t)blockIdx.x * blockDim.x + threadIdx.x; i < (size_t)NN * HH; i += stride)
            Y[i] = tf32r(fmaf(X[i], s, t));
    } else {
        for (size_t i = (size_t)blockIdx.x * blockDim.x + threadIdx.x; i < (size_t)NN * HH; i += stride)
            Y[i] = fmaf(X[i], s, t);
    }
}

// ---------------- launcher ----------------
extern "C" void kernel_launch(void* const* d_in, const int* in_sizes, int n_in,
                              void* d_out, int out_size) {
    (void)in_sizes; (void)n_in; (void)out_size;
    const float* x      = (const float*)d_in[0];
    const float* w      = (const float*)d_in[1];
    const int*   src    = (const int*)d_in[2];
    const int*   dst    = (const int*)d_in[3];
    const float* aW     = (const float*)d_in[4];
    const float* ab     = (const float*)d_in[5];
    const float* bW0    = (const float*)d_in[6];
    const float* bb0    = (const float*)d_in[7];
    const float* gamma0 = (const float*)d_in[8];
    const float* beta0  = (const float*)d_in[9];
    const float* bondW  = (const float*)d_in[10];
    const float* bondb  = (const float*)d_in[11];
    const float* W1     = (const float*)d_in[12];
    const float* b1     = (const float*)d_in[13];
    const float* W2     = (const float*)d_in[14];
    const float* b2     = (const float*)d_in[15];
    const float* gamma1 = (const float*)d_in[16];
    const float* beta1  = (const float*)d_in[17];
    const float* gamma2 = (const float*)d_in[18];
    const float* beta2  = (const float*)d_in[19];

    float *p_degf, *p_ws, *p_h, *p_zr, *p_h1, *p_feat, *p_stats, *p_sc, *p_sh;
    float *p_xr, *p_aWr, *p_bW0r, *p_bondWr, *p_W1r, *p_W2r;
    cudaGetSymbolAddress((void**)&p_degf, g_degf);
    cudaGetSymbolAddress((void**)&p_ws, g_ws);
    cudaGetSymbolAddress((void**)&p_h, g_h);
    cudaGetSymbolAddress((void**)&p_zr, g_zr);
    cudaGetSymbolAddress((void**)&p_h1, g_h1);
    cudaGetSymbolAddress((void**)&p_feat, g_feat);
    cudaGetSymbolAddress((void**)&p_stats, g_stats);
    cudaGetSymbolAddress((void**)&p_sc, g_sc);
    cudaGetSymbolAddress((void**)&p_sh, g_sh);
    cudaGetSymbolAddress((void**)&p_xr, g_xr);
    cudaGetSymbolAddress((void**)&p_aWr, g_aWr);
    cudaGetSymbolAddress((void**)&p_bW0r, g_bW0r);
    cudaGetSymbolAddress((void**)&p_bondWr, g_bondWr);
    cudaGetSymbolAddress((void**)&p_W1r, g_W1r);
    cudaGetSymbolAddress((void**)&p_W2r, g_W2r);

    const int EB = (EE + 255) / 256;
    const int WB = (NN * 32 + 255) / 256;
    const dim3 gg(HH / 128, (NN + 127) / 128);  // (2, 391)

    init_k<<<256, 256>>>();
    hist_k<<<EB, 256>>>(dst);
    scan_k<<<1, 1024>>>();
    scatter_k<<<EB, 256>>>(src, dst);
    ws_k<<<WB, 256>>>(w);

    // pre-round all static MMA operands (bit-identical to R5's in-loop cvt.rna)
    preround_k<<<(NN * AA + 255) / 256, 256>>>(x, p_xr, NN * AA);
    preround_k<<<(AA * HH + 255) / 256, 256>>>(aW, p_aWr, AA * HH);
    preround_k<<<(BB * HH + 255) / 256, 256>>>(bW0, p_bW0r, BB * HH);
    preround_k<<<(LLAYERS * BB * HH + 255) / 256, 256>>>(bondW, p_bondWr, LLAYERS * BB * HH);
    preround_k<<<(LLAYERS * HH * HH + 255) / 256, 256>>>(W1, p_W1r, LLAYERS * HH * HH);
    preround_k<<<(LLAYERS * HH * HH + 255) / 256, 256>>>(W2, p_W2r, LLAYERS * HH * HH);

    float* X = p_feat;   // raw (pre-BN) layer output
    float* Y = p_h1;
    float* Z = p_h;

    // ---- first layer: X = relu(x@aW + ws@bW0 + ab + deg*bb0); fused stats0 ----
    gemm_tc<<<gg, 256>>>(p_xr, p_aWr, AA, p_ws, p_bW0r, BB, ab, bb0, p_degf,
                         nullptr, nullptr, nullptr, p_stats, X);
    scsh_k<<<1, 256>>>(p_stats, gamma0, beta0, p_sc, p_sh);
    int pidx = 0;

    for (int l = 0; l < LLAYERS; l++) {
        int midx = 1 + 2 * l;
        int oidx = 2 + 2 * l;
        const float* scp = p_sc + pidx * HH;
        const float* shp = p_sh + pidx * HH;
        // Y = tf32r(sc_p * seg(X[src]) + deg * sh_p)   (centered BEFORE rounding)
        spmm_k<<<WB, 256>>>(X, Y, scp, shp);
        // Z = relu(Y@W1 + ws@bondW + b1 + deg*bondb); fused stats mid
        gemm_tc<<<gg, 256>>>(Y, p_W1r + (size_t)l * HH * HH, HH,
                             p_ws, p_bondWr + (size_t)l * BB * HH, BB,
                             b1 + l * HH, bondb + l * HH, p_degf,
                             nullptr, nullptr, nullptr,
                             p_stats + midx * 2 * HH, Z);
        scsh_k<<<1, 256>>>(p_stats + midx * 2 * HH, gamma1 + l * HH, beta1 + l * HH,
                           p_sc + midx * HH, p_sh + midx * HH);
        // Zr = tf32r(BN(Z))  (centered BEFORE rounding)
        aff_k<<<4096, 256>>>(Z, p_zr, p_sc + midx * HH, p_sh + midx * HH, 1);
        // Y = relu(Zr@W2 + b2 + (X*sc_p + sh_p)); fused stats out
        gemm_tc<<<gg, 256>>>(p_zr, p_W2r + (size_t)l * HH * HH, HH,
                             nullptr, nullptr, 0,
                             b2 + l * HH, nullptr, nullptr,
                             X, scp, shp,
                             p_stats + oidx * 2 * HH, Y);
        scsh_k<<<1, 256>>>(p_stats + oidx * 2 * HH, gamma2 + l * HH, beta2 + l * HH,
                           p_sc + oidx * HH, p_sh + oidx * HH);
        float* tmp = X; X = Y; Y = tmp;
        pidx = oidx;
    }

    // final: out = X*sc_last + sh_last (no rounding)
    aff_k<<<4096, 256>>>(X, (float*)d_out, p_sc + pidx * HH, p_sh + pidx * HH, 0);
}

// round 13
// speedup vs baseline: 2.2567x; 1.0859x over previous
#include <cuda_runtime.h>
#include <cuda_fp16.h>
#include <cstddef>
#include <cstdint>

#define NN 50000
#define EE 800000
#define HH 256
#define AA 128
#define BB 32
#define LL 3
#define BNEPS 1e-5f

typedef __half hf;

// ---------------- device scratch ----------------
__device__ int g_deg[NN];
__device__ int g_rowcur[NN];
__device__ int g_rowptr[NN + 1];
__device__ int g_colsrc[EE];
__device__ int g_eidx[EE];
__device__ __align__(16) float g_degf[NN];
__device__ __align__(16) float g_X[(size_t)NN * HH];
__device__ __align__(16) float g_Y[(size_t)NN * HH];
__device__ __align__(16) float g_Z[(size_t)NN * HH];
__device__ __align__(16) hf g_x16[(size_t)NN * AA];
__device__ __align__(16) hf g_ws16[(size_t)NN * BB];
__device__ __align__(16) hf g_y16[(size_t)NN * HH];
__device__ __align__(16) hf g_z16[(size_t)NN * HH];
__device__ __align__(16) hf g_aWt[HH * AA];
__device__ __align__(16) hf g_bW0t[HH * BB];
__device__ __align__(16) hf g_bondt[LL * HH * BB];
__device__ __align__(16) hf g_W1t[LL * HH * HH];
__device__ __align__(16) hf g_W2t[LL * HH * HH];
__device__ float g_stats[7 * 2 * HH];
__device__ float g_sc[7 * HH];
__device__ float g_sh[7 * HH];

// ---------------- helpers ----------------
__device__ __forceinline__ void cpa16(const hf* dst, const hf* src, bool ok) {
    uint32_t d = (uint32_t)__cvta_generic_to_shared(dst);
    int sz = ok ? 16 : 0;
    asm volatile("cp.async.ca.shared.global [%0], [%1], 16, %2;" :: "r"(d), "l"(src), "r"(sz));
}
__device__ __forceinline__ void mmah(float* d, const uint32_t* a, uint32_t b0, uint32_t b1) {
    asm volatile(
        "mma.sync.aligned.m16n8k16.row.col.f32.f16.f16.f32 "
        "{%0,%1,%2,%3}, {%4,%5,%6,%7}, {%8,%9}, {%0,%1,%2,%3};"
        : "+f"(d[0]), "+f"(d[1]), "+f"(d[2]), "+f"(d[3])
        : "r"(a[0]), "r"(a[1]), "r"(a[2]), "r"(a[3]), "r"(b0), "r"(b1));
}

// ---------------- setup ----------------
__global__ void init_k() {
    int i = blockIdx.x * blockDim.x + threadIdx.x, st = gridDim.x * blockDim.x;
    for (int t = i; t < NN; t += st) { g_deg[t] = 0; g_rowcur[t] = 0; }
    for (int t = i; t < 7 * 2 * HH; t += st) g_stats[t] = 0.f;
}
__global__ void hist_k(const int* __restrict__ dst) {
    int e = blockIdx.x * blockDim.x + threadIdx.x;
    if (e < EE) atomicAdd(&g_deg[dst[e]], 1);
}
__global__ void scan_k() {
    __shared__ int part[1024];
    const int t = threadIdx.x, CH = (NN + 1023) / 1024, base = t * CH;
    int s = 0;
    for (int i = 0; i < CH; i++) { int x = base + i; if (x < NN) s += g_deg[x]; }
    part[t] = s;
    __syncthreads();
    for (int off = 1; off < 1024; off <<= 1) {
        int v = (t >= off) ? part[t - off] : 0;
        __syncthreads(); part[t] += v; __syncthreads();
    }
    int run = (t == 0) ? 0 : part[t - 1];
    for (int i = 0; i < CH; i++) {
        int x = base + i;
        if (x < NN) { int d = g_deg[x]; g_rowptr[x] = run; g_degf[x] = (float)d; run += d; }
    }
    if (t == 1023) g_rowptr[NN] = part[1023];
}
__global__ void scatter_k(const int* __restrict__ src, const int* __restrict__ dst) {
    int e = blockIdx.x * blockDim.x + threadIdx.x;
    if (e < EE) {
        int d = dst[e];
        int p = g_rowptr[d] + atomicAdd(&g_rowcur[d], 1);
        g_colsrc[p] = src[e]; g_eidx[p] = e;
    }
}
__global__ void ws_k(const float* __restrict__ w) {
    int gw = (blockIdx.x * blockDim.x + threadIdx.x) >> 5, lane = threadIdx.x & 31;
    if (gw >= NN) return;
    int s = g_rowptr[gw], e = g_rowptr[gw + 1];
    float acc = 0.f;
    for (int j = s; j < e; j++) acc += __ldg(&w[(size_t)g_eidx[j] * BB + lane]);
    g_ws16[(size_t)gw * BB + lane] = __float2half(acc);
}
__global__ void xc_k(const float* __restrict__ x) {
    int i = blockIdx.x * blockDim.x + threadIdx.x;
    if (i < NN * AA) g_x16[i] = __float2half(x[i]);
}
// W [L][K,256] -> Wt [L][256,K] half
__global__ void wt_k(const float* __restrict__ W, int K, hf* __restrict__ out) {
    int l = blockIdx.y;
    int i = blockIdx.x * blockDim.x + threadIdx.x;
    if (i >= HH * K) return;
    int n = i / K, k = i % K;
    out[(size_t)l * HH * K + i] = __float2half(W[(size_t)l * K * HH + (size_t)k * HH + n]);
}

// ---------------- SpMM: BN-affine fused, half output ----------------
__global__ void spmm_k(const float* __restrict__ F, hf* __restrict__ O,
                       const float* __restrict__ sc, const float* __restrict__ sh) {
    int gw = (blockIdx.x * blockDim.x + threadIdx.x) >> 5, lane = threadIdx.x & 31;
    if (gw >= NN) return;
    int s = g_rowptr[gw], e = g_rowptr[gw + 1];
    float4 a0 = make_float4(0, 0, 0, 0), a1 = make_float4(0, 0, 0, 0);
    for (int j = s; j < e; j++) {
        const float4* r = reinterpret_cast<const float4*>(F + (size_t)g_colsrc[j] * HH);
        float4 v0 = __ldg(&r[lane]), v1 = __ldg(&r[lane + 32]);
        a0.x += v0.x; a0.y += v0.y; a0.z += v0.z; a0.w += v0.w;
        a1.x += v1.x; a1.y += v1.y; a1.z += v1.z; a1.w += v1.w;
    }
    float dg = (float)(e - s);
    float4 s0 = *reinterpret_cast<const float4*>(sc + lane * 4);
    float4 s1 = *reinterpret_cast<const float4*>(sc + (lane + 32) * 4);
    float4 t0 = *reinterpret_cast<const float4*>(sh + lane * 4);
    float4 t1 = *reinterpret_cast<const float4*>(sh + (lane + 32) * 4);
    __half2* o = reinterpret_cast<__half2*>(O + (size_t)gw * HH);
    o[lane * 2 + 0] = __floats2half2_rn(fmaf(a0.x, s0.x, dg * t0.x), fmaf(a0.y, s0.y, dg * t0.y));
    o[lane * 2 + 1] = __floats2half2_rn(fmaf(a0.z, s0.z, dg * t0.z), fmaf(a0.w, s0.w, dg * t0.w));
    o[(lane + 32) * 2 + 0] = __floats2half2_rn(fmaf(a1.x, s1.x, dg * t1.x), fmaf(a1.y, s1.y, dg * t1.y));
    o[(lane + 32) * 2 + 1] = __floats2half2_rn(fmaf(a1.z, s1.z, dg * t1.z), fmaf(a1.w, s1.w, dg * t1.w));
}

// ---------------- fp16 tensor-core GEMM, fused stats ----------------
// C = relu(A1@B1' + A2@B2' + bias1 + deg*bias2 + (addraw*asc+ash)); B' = [N,K] row-major.
__global__ void __launch_bounds__(256, 2) gemm_h(
    const hf* __restrict__ A1, const hf* __restrict__ B1, int K1,
    const hf* __restrict__ A2, const hf* __restrict__ B2, int K2,
    const float* __restrict__ bias1, const float* __restrict__ bias2,
    const float* __restrict__ degf,
    const float* __restrict__ addraw, const float* __restrict__ asc,
    const float* __restrict__ ash,
    float* __restrict__ stout, float* __restrict__ C)
{
    __shared__ hf As[2][128][24];   // [m][k16], 48B row stride (conflict-free)
    __shared__ hf Bs[2][128][24];   // [n][k16]
    const int tid = threadIdx.x, lane = tid & 31, warp = tid >> 5;
    const int wm = (warp & 3) * 32, wn = (warp >> 2) * 64;
    const int rowBase = blockIdx.y * 128, colBase = blockIdx.x * 128;
    const int gr = lane >> 2, fc = lane & 3;

    float acc[2][8][4];
#pragma unroll
    for (int mt = 0; mt < 2; mt++)
#pragma unroll
        for (int nt = 0; nt < 8; nt++)
#pragma unroll
            for (int q = 0; q < 4; q++) acc[mt][nt][q] = 0.f;

    int buf = 0;
#pragma unroll 1
    for (int part = 0; part < 2; part++) {
        const hf* Ap = part ? A2 : A1;
        const hf* Bp = part ? B2 : B1;
        const int K = part ? K2 : K1;
        if (Ap == nullptr) continue;
        const int T = K / 16;
        {
            int m = tid >> 1, c2 = tid & 1;
            int gm = rowBase + m;
            bool ok = gm < NN;
            cpa16(&As[buf][m][c2 * 8], Ap + (size_t)(ok ? gm : 0) * K + c2 * 8, ok);
            cpa16(&Bs[buf][m][c2 * 8], Bp + (size_t)(colBase + m) * K + c2 * 8, true);
            asm volatile("cp.async.commit_group;");
        }
#pragma unroll 1
        for (int it = 0; it < T; it++) {
            if (it + 1 < T) {
                int k0 = (it + 1) * 16, nb = buf ^ 1;
                int m = tid >> 1, c2 = tid & 1;
                int gm = rowBase + m;
                bool ok = gm < NN;
                cpa16(&As[nb][m][c2 * 8], Ap + (size_t)(ok ? gm : 0) * K + k0 + c2 * 8, ok);
                cpa16(&Bs[nb][m][c2 * 8], Bp + (size_t)(colBase + m) * K + k0 + c2 * 8, true);
                asm volatile("cp.async.commit_group;");
                asm volatile("cp.async.wait_group 1;");
            } else {
                asm volatile("cp.async.wait_group 0;");
            }
            __syncthreads();

            uint32_t a[2][4];
#pragma unroll
            for (int mt = 0; mt < 2; mt++) {
                int r0 = wm + mt * 16 + gr;
                a[mt][0] = *reinterpret_cast<const uint32_t*>(&As[buf][r0][2 * fc]);
                a[mt][1] = *reinterpret_cast<const uint32_t*>(&As[buf][r0 + 8][2 * fc]);
                a[mt][2] = *reinterpret_cast<const uint32_t*>(&As[buf][r0][2 * fc + 8]);
                a[mt][3] = *reinterpret_cast<const uint32_t*>(&As[buf][r0 + 8][2 * fc + 8]);
            }
#pragma unroll
            for (int nt = 0; nt < 8; nt++) {
                int bn = wn + nt * 8 + gr;
                uint32_t b0 = *reinterpret_cast<const uint32_t*>(&Bs[buf][bn][2 * fc]);
                uint32_t b1 = *reinterpret_cast<const uint32_t*>(&Bs[buf][bn][2 * fc + 8]);
                mmah(acc[0][nt], a[0], b0, b1);
                mmah(acc[1][nt], a[1], b0, b1);
            }
            __syncthreads();
            buf ^= 1;
        }
    }

    // epilogue + fused stats
    float cs0[8], cs1[8], cq0[8], cq1[8];
#pragma unroll
    for (int nt = 0; nt < 8; nt++) { cs0[nt] = 0.f; cs1[nt] = 0.f; cq0[nt] = 0.f; cq1[nt] = 0.f; }
#pragma unroll
    for (int mt = 0; mt < 2; mt++) {
        int rbase = rowBase + wm + mt * 16 + gr;
#pragma unroll
        for (int ph = 0; ph < 2; ph++) {
            int rr = rbase + 8 * ph;
            if (rr < NN) {
                float dg = bias2 ? degf[rr] : 0.f;
#pragma unroll
                for (int nt = 0; nt < 8; nt++) {
                    int cc = colBase + wn + nt * 8 + 2 * fc;
                    float v0 = acc[mt][nt][2 * ph + 0] + bias1[cc];
                    float v1 = acc[mt][nt][2 * ph + 1] + bias1[cc + 1];
                    if (bias2) {
                        v0 = fmaf(dg, bias2[cc], v0);
                        v1 = fmaf(dg, bias2[cc + 1], v1);
                    }
                    if (addraw) {
                        float2 ar = *reinterpret_cast<const float2*>(addraw + (size_t)rr * HH + cc);
                        v0 = fmaf(ar.x, asc[cc], v0 + ash[cc]);
                        v1 = fmaf(ar.y, asc[cc + 1], v1 + ash[cc + 1]);
                    }
                    v0 = fmaxf(v0, 0.f);
                    v1 = fmaxf(v1, 0.f);
                    cs0[nt] += v0; cq0[nt] = fmaf(v0, v0, cq0[nt]);
                    cs1[nt] += v1; cq1[nt] = fmaf(v1, v1, cq1[nt]);
                    *reinterpret_cast<float2*>(C + (size_t)rr * HH + cc) = make_float2(v0, v1);
                }
            }
        }
    }
    if (stout) {
#pragma unroll
        for (int nt = 0; nt < 8; nt++) {
#pragma unroll
            for (int off = 4; off < 32; off <<= 1) {
                cs0[nt] += __shfl_xor_sync(0xffffffffu, cs0[nt], off);
                cs1[nt] += __shfl_xor_sync(0xffffffffu, cs1[nt], off);
                cq0[nt] += __shfl_xor_sync(0xffffffffu, cq0[nt], off);
                cq1[nt] += __shfl_xor_sync(0xffffffffu, cq1[nt], off);
            }
            if (lane < 4) {
                int cc = colBase + wn + nt * 8 + 2 * lane;
                atomicAdd(&stout[cc], cs0[nt]);
                atomicAdd(&stout[cc + 1], cs1[nt]);
                atomicAdd(&stout[HH + cc], cq0[nt]);
                atomicAdd(&stout[HH + cc + 1], cq1[nt]);
            }
        }
    }
}

// ---------------- scsh / affine ----------------
__global__ void scsh_k(const float* __restrict__ st, const float* __restrict__ ga,
                       const float* __restrict__ be, float* __restrict__ sc,
                       float* __restrict__ sh) {
    int c = threadIdx.x;
    const float invN = 1.0f / (float)NN;
    float mu = st[c] * invN;
    float var = st[HH + c] * invN - mu * mu;
    float s = rsqrtf(var + BNEPS) * ga[c];
    sc[c] = s; sh[c] = be[c] - mu * s;
}
__global__ void affh_k(const float* __restrict__ X, hf* __restrict__ O,
                       const float* __restrict__ sc, const float* __restrict__ sh) {
    const int c = threadIdx.x;  // stride multiple of 256 keeps column fixed
    float s = sc[c], t = sh[c];
    size_t stride = (size_t)gridDim.x * blockDim.x;
    for (size_t i = (size_t)blockIdx.x * blockDim.x + threadIdx.x; i < (size_t)NN * HH; i += stride)
        O[i] = __float2half(fmaf(X[i], s, t));
}
__global__ void aff_k(const float* __restrict__ X, float* __restrict__ Y,
                      const float* __restrict__ sc, const float* __restrict__ sh) {
    const int c = threadIdx.x;
    float s = sc[c], t = sh[c];
    size_t stride = (size_t)gridDim.x * blockDim.x;
    for (size_t i = (size_t)blockIdx.x * blockDim.x + threadIdx.x; i < (size_t)NN * HH; i += stride)
        Y[i] = fmaf(X[i], s, t);
}

// ---------------- launcher ----------------
extern "C" void kernel_launch(void* const* d_in, const int* in_sizes, int n_in,
                              void* d_out, int out_size) {
    (void)in_sizes; (void)n_in; (void)out_size;
    const float* x = (const float*)d_in[0];
    const float* w = (const float*)d_in[1];
    const int* src = (const int*)d_in[2];
    const int* dst = (const int*)d_in[3];
    const float* aW = (const float*)d_in[4];
    const float* ab = (const float*)d_in[5];
    const float* bW0 = (const float*)d_in[6];
    const float* bb0 = (const float*)d_in[7];
    const float* gamma0 = (const float*)d_in[8];
    const float* beta0 = (const float*)d_in[9];
    const float* bondW = (const float*)d_in[10];
    const float* bondb = (const float*)d_in[11];
    const float* W1 = (const float*)d_in[12];
    const float* b1 = (const float*)d_in[13];
    const float* W2 = (const float*)d_in[14];
    const float* b2 = (const float*)d_in[15];
    const float* gamma1 = (const float*)d_in[16];
    const float* beta1 = (const float*)d_in[17];
    const float* gamma2 = (const float*)d_in[18];
    const float* beta2 = (const float*)d_in[19];

#define GSA(p, s) cudaGetSymbolAddress((void**)&p, s)
    float *pdeg, *pX, *pY, *pZ, *pst, *psc, *psh;
    hf *px16, *pws, *py16, *pz16, *paW, *pbW0, *pbond, *pW1, *pW2;
    GSA(pdeg, g_degf); GSA(pX, g_X); GSA(pY, g_Y); GSA(pZ, g_Z);
    GSA(pst, g_stats); GSA(psc, g_sc); GSA(psh, g_sh);
    GSA(px16, g_x16); GSA(pws, g_ws16); GSA(py16, g_y16); GSA(pz16, g_z16);
    GSA(paW, g_aWt); GSA(pbW0, g_bW0t); GSA(pbond, g_bondt);
    GSA(pW1, g_W1t); GSA(pW2, g_W2t);

    const int EB = (EE + 255) / 256, WB = (NN * 32 + 255) / 256;
    const dim3 gg(HH / 128, (NN + 127) / 128);  // (2, 391)

    init_k<<<256, 256>>>();
    hist_k<<<EB, 256>>>(dst);
    scan_k<<<1, 1024>>>();
    scatter_k<<<EB, 256>>>(src, dst);
    ws_k<<<WB, 256>>>(w);
    xc_k<<<(NN * AA + 255) / 256, 256>>>(x);
    wt_k<<<dim3((HH * AA + 255) / 256, 1), 256>>>(aW, AA, paW);
    wt_k<<<dim3((HH * BB + 255) / 256, 1), 256>>>(bW0, BB, pbW0);
    wt_k<<<dim3((HH * BB + 255) / 256, LL), 256>>>(bondW, BB, pbond);
    wt_k<<<dim3((HH * HH + 255) / 256, LL), 256>>>(W1, HH, pW1);
    wt_k<<<dim3((HH * HH + 255) / 256, LL), 256>>>(W2, HH, pW2);

    float* X = pX; float* Y = pY; float* Z = pZ;
    // ---- first layer ----
    gemm_h<<<gg, 256>>>(px16, paW, AA, pws, pbW0, BB, ab, bb0, pdeg,
                        nullptr, nullptr, nullptr, pst, X);
    scsh_k<<<1, 256>>>(pst, gamma0, beta0, psc, psh);
    int pidx = 0;
    for (int l = 0; l < LL; l++) {
        int midx = 1 + 2 * l, oidx = 2 + 2 * l;
        const float* scp = psc + pidx * HH;
        const float* shp = psh + pidx * HH;
        spmm_k<<<WB, 256>>>(X, py16, scp, shp);
        gemm_h<<<gg, 256>>>(py16, pW1 + (size_t)l * HH * HH, HH,
                            pws, pbond + (size_t)l * HH * BB, BB,
                            b1 + l * HH, bondb + l * HH, pdeg,
                            nullptr, nullptr, nullptr,
                            pst + midx * 2 * HH, Z);
        scsh_k<<<1, 256>>>(pst + midx * 2 * HH, gamma1 + l * HH, beta1 + l * HH,
                           psc + midx * HH, psh + midx * HH);
        affh_k<<<4096, 256>>>(Z, pz16, psc + midx * HH, psh + midx * HH);
        gemm_h<<<gg, 256>>>(pz16, pW2 + (size_t)l * HH * HH, HH,
                            nullptr, nullptr, 0,
                            b2 + l * HH, nullptr, nullptr,
                            X, scp, shp,
                            pst + oidx * 2 * HH, Y);
        scsh_k<<<1, 256>>>(pst + oidx * 2 * HH, gamma2 + l * HH, beta2 + l * HH,
                           psc + oidx * HH, psh + oidx * HH);
        float* tmp = X; X = Y; Y = tmp;
        pidx = oidx;
    }
    aff_k<<<4096, 256>>>(X, (float*)d_out, psc + pidx * HH, psh + pidx * HH);
}

// round 15
// speedup vs baseline: 2.4906x; 1.1037x over previous
#include <cuda_runtime.h>
#include <cuda_fp16.h>
#include <cstddef>
#include <cstdint>

#define NN 50000
#define EE 800000
#define HH 256
#define AA 128
#define BB 32
#define LL 3
#define BNEPS 1e-5f

typedef __half hf;

// ---------------- device scratch ----------------
__device__ int g_deg[NN];
__device__ int g_rowcur[NN];
__device__ int g_rowptr[NN + 1];
__device__ int g_colsrc[EE];
__device__ int g_eidx[EE];
__device__ __align__(16) float g_degf[NN];
__device__ __align__(16) float g_X[(size_t)NN * HH];
__device__ __align__(16) float g_Y[(size_t)NN * HH];
__device__ __align__(16) float g_Z[(size_t)NN * HH];
__device__ __align__(16) hf g_Xh[(size_t)NN * HH];   // fp16 copy of X for gather
__device__ __align__(16) hf g_Yh[(size_t)NN * HH];
__device__ __align__(16) hf g_x16[(size_t)NN * AA];
__device__ __align__(16) hf g_ws16[(size_t)NN * BB];
__device__ __align__(16) hf g_y16[(size_t)NN * HH];
__device__ __align__(16) hf g_z16[(size_t)NN * HH];
__device__ __align__(16) hf g_aWt[HH * AA];
__device__ __align__(16) hf g_bW0t[HH * BB];
__device__ __align__(16) hf g_bondt[LL * HH * BB];
__device__ __align__(16) hf g_W1t[LL * HH * HH];
__device__ __align__(16) hf g_W2t[LL * HH * HH];
__device__ float g_stats[7 * 2 * HH];
__device__ float g_sc[7 * HH];
__device__ float g_sh[7 * HH];

// ---------------- helpers ----------------
__device__ __forceinline__ void cpa16(const hf* dst, const hf* src, bool ok) {
    uint32_t d = (uint32_t)__cvta_generic_to_shared(dst);
    int sz = ok ? 16 : 0;
    asm volatile("cp.async.ca.shared.global [%0], [%1], 16, %2;" :: "r"(d), "l"(src), "r"(sz));
}
__device__ __forceinline__ void mmah(float* d, const uint32_t* a, uint32_t b0, uint32_t b1) {
    asm volatile(
        "mma.sync.aligned.m16n8k16.row.col.f32.f16.f16.f32 "
        "{%0,%1,%2,%3}, {%4,%5,%6,%7}, {%8,%9}, {%0,%1,%2,%3};"
        : "+f"(d[0]), "+f"(d[1]), "+f"(d[2]), "+f"(d[3])
        : "r"(a[0]), "r"(a[1]), "r"(a[2]), "r"(a[3]), "r"(b0), "r"(b1));
}

// ---------------- setup ----------------
__global__ void init_k() {
    int i = blockIdx.x * blockDim.x + threadIdx.x, st = gridDim.x * blockDim.x;
    for (int t = i; t < NN; t += st) { g_deg[t] = 0; g_rowcur[t] = 0; }
    for (int t = i; t < 7 * 2 * HH; t += st) g_stats[t] = 0.f;
}
__global__ void hist_k(const int* __restrict__ dst) {
    int e = blockIdx.x * blockDim.x + threadIdx.x;
    if (e < EE) atomicAdd(&g_deg[dst[e]], 1);
}
__global__ void scan_k() {
    __shared__ int part[1024];
    const int t = threadIdx.x, CH = (NN + 1023) / 1024, base = t * CH;
    int s = 0;
    for (int i = 0; i < CH; i++) { int x = base + i; if (x < NN) s += g_deg[x]; }
    part[t] = s;
    __syncthreads();
    for (int off = 1; off < 1024; off <<= 1) {
        int v = (t >= off) ? part[t - off] : 0;
        __syncthreads(); part[t] += v; __syncthreads();
    }
    int run = (t == 0) ? 0 : part[t - 1];
    for (int i = 0; i < CH; i++) {
        int x = base + i;
        if (x < NN) { int d = g_deg[x]; g_rowptr[x] = run; g_degf[x] = (float)d; run += d; }
    }
    if (t == 1023) g_rowptr[NN] = part[1023];
}
__global__ void scatter_k(const int* __restrict__ src, const int* __restrict__ dst) {
    int e = blockIdx.x * blockDim.x + threadIdx.x;
    if (e < EE) {
        int d = dst[e];
        int p = g_rowptr[d] + atomicAdd(&g_rowcur[d], 1);
        g_colsrc[p] = src[e]; g_eidx[p] = e;
    }
}
__global__ void ws_k(const float* __restrict__ w) {
    int gw = (blockIdx.x * blockDim.x + threadIdx.x) >> 5, lane = threadIdx.x & 31;
    if (gw >= NN) return;
    int s = g_rowptr[gw], e = g_rowptr[gw + 1];
    float acc = 0.f;
    for (int j = s; j < e; j++) acc += __ldg(&w[(size_t)g_eidx[j] * BB + lane]);
    g_ws16[(size_t)gw * BB + lane] = __float2half(acc);
}
__global__ void xc_k(const float* __restrict__ x) {
    int i = blockIdx.x * blockDim.x + threadIdx.x;
    if (i < NN * AA) g_x16[i] = __float2half(x[i]);
}
__global__ void wt_k(const float* __restrict__ W, int K, hf* __restrict__ out) {
    int l = blockIdx.y;
    int i = blockIdx.x * blockDim.x + threadIdx.x;
    if (i >= HH * K) return;
    int n = i / K, k = i % K;
    out[(size_t)l * HH * K + i] = __float2half(W[(size_t)l * K * HH + (size_t)k * HH + n]);
}

// ---------------- SpMM (fp16 gather): O=half(sc*sum F16[src] + deg*sh) ----------------
__global__ void spmm_k(const hf* __restrict__ F, hf* __restrict__ O,
                       const float* __restrict__ sc, const float* __restrict__ sh) {
    int gw = (blockIdx.x * blockDim.x + threadIdx.x) >> 5, lane = threadIdx.x & 31;
    if (gw >= NN) return;
    int s = g_rowptr[gw], e = g_rowptr[gw + 1];
    float acc[8];
#pragma unroll
    for (int u = 0; u < 8; u++) acc[u] = 0.f;
    for (int j = s; j < e; j++) {
        const uint4* r = reinterpret_cast<const uint4*>(F + (size_t)g_colsrc[j] * HH);
        uint4 v = __ldg(&r[lane]);
        __half2 h0 = *reinterpret_cast<__half2*>(&v.x);
        __half2 h1 = *reinterpret_cast<__half2*>(&v.y);
        __half2 h2 = *reinterpret_cast<__half2*>(&v.z);
        __half2 h3 = *reinterpret_cast<__half2*>(&v.w);
        float2 f0 = __half22float2(h0), f1 = __half22float2(h1);
        float2 f2 = __half22float2(h2), f3 = __half22float2(h3);
        acc[0] += f0.x; acc[1] += f0.y; acc[2] += f1.x; acc[3] += f1.y;
        acc[4] += f2.x; acc[5] += f2.y; acc[6] += f3.x; acc[7] += f3.y;
    }
    float dg = (float)(e - s);
    int c0 = lane * 8;
    float4 sA = *reinterpret_cast<const float4*>(sc + c0);
    float4 sB = *reinterpret_cast<const float4*>(sc + c0 + 4);
    float4 tA = *reinterpret_cast<const float4*>(sh + c0);
    float4 tB = *reinterpret_cast<const float4*>(sh + c0 + 4);
    float o[8];
    o[0] = fmaf(acc[0], sA.x, dg * tA.x); o[1] = fmaf(acc[1], sA.y, dg * tA.y);
    o[2] = fmaf(acc[2], sA.z, dg * tA.z); o[3] = fmaf(acc[3], sA.w, dg * tA.w);
    o[4] = fmaf(acc[4], sB.x, dg * tB.x); o[5] = fmaf(acc[5], sB.y, dg * tB.y);
    o[6] = fmaf(acc[6], sB.z, dg * tB.z); o[7] = fmaf(acc[7], sB.w, dg * tB.w);
    uint4 w;
    __half2 p0 = __floats2half2_rn(o[0], o[1]), p1 = __floats2half2_rn(o[2], o[3]);
    __half2 p2 = __floats2half2_rn(o[4], o[5]), p3 = __floats2half2_rn(o[6], o[7]);
    w.x = *reinterpret_cast<uint32_t*>(&p0); w.y = *reinterpret_cast<uint32_t*>(&p1);
    w.z = *reinterpret_cast<uint32_t*>(&p2); w.w = *reinterpret_cast<uint32_t*>(&p3);
    reinterpret_cast<uint4*>(O + (size_t)gw * HH)[lane] = w;
}

// ---------------- fp16 tensor-core GEMM, k32 steps, fused stats + hf copy ----------------
__global__ void __launch_bounds__(256, 2) gemm_h(
    const hf* __restrict__ A1, const hf* __restrict__ B1, int K1,
    const hf* __restrict__ A2, const hf* __restrict__ B2, int K2,
    const float* __restrict__ bias1, const float* __restrict__ bias2,
    const float* __restrict__ degf,
    const float* __restrict__ addraw, const float* __restrict__ asc,
    const float* __restrict__ ash,
    float* __restrict__ stout, float* __restrict__ C, hf* __restrict__ Chf)
{
    __shared__ hf As[2][128][40];   // [m][k32], 80B stride (conflict-free)
    __shared__ hf Bs[2][128][40];
    const int tid = threadIdx.x, lane = tid & 31, warp = tid >> 5;
    const int wm = (warp & 3) * 32, wn = (warp >> 2) * 64;
    const int rowBase = blockIdx.y * 128, colBase = blockIdx.x * 128;
    const int gr = lane >> 2, fc = lane & 3;

    float acc[2][8][4];
#pragma unroll
    for (int mt = 0; mt < 2; mt++)
#pragma unroll
        for (int nt = 0; nt < 8; nt++)
#pragma unroll
            for (int q = 0; q < 4; q++) acc[mt][nt][q] = 0.f;

    int buf = 0;
#pragma unroll 1
    for (int part = 0; part < 2; part++) {
        const hf* Ap = part ? A2 : A1;
        const hf* Bp = part ? B2 : B1;
        const int K = part ? K2 : K1;
        if (Ap == nullptr) continue;
        const int T = K / 32;
        {
#pragma unroll
            for (int i = 0; i < 2; i++) {
                int ch = i * 256 + tid, m = ch >> 2, c4 = ch & 3;
                int gm = rowBase + m;
                bool ok = gm < NN;
                cpa16(&As[buf][m][c4 * 8], Ap + (size_t)(ok ? gm : 0) * K + c4 * 8, ok);
                cpa16(&Bs[buf][m][c4 * 8], Bp + (size_t)(colBase + m) * K + c4 * 8, true);
            }
            asm volatile("cp.async.commit_group;");
        }
#pragma unroll 1
        for (int it = 0; it < T; it++) {
            if (it + 1 < T) {
                int k0 = (it + 1) * 32, nb = buf ^ 1;
#pragma unroll
                for (int i = 0; i < 2; i++) {
                    int ch = i * 256 + tid, m = ch >> 2, c4 = ch & 3;
                    int gm = rowBase + m;
                    bool ok = gm < NN;
                    cpa16(&As[nb][m][c4 * 8], Ap + (size_t)(ok ? gm : 0) * K + k0 + c4 * 8, ok);
                    cpa16(&Bs[nb][m][c4 * 8], Bp + (size_t)(colBase + m) * K + k0 + c4 * 8, true);
                }
                asm volatile("cp.async.commit_group;");
                asm volatile("cp.async.wait_group 1;");
            } else {
                asm volatile("cp.async.wait_group 0;");
            }
            __syncthreads();
#pragma unroll
            for (int ks = 0; ks < 32; ks += 16) {
                uint32_t a[2][4];
#pragma unroll
                for (int mt = 0; mt < 2; mt++) {
                    int r0 = wm + mt * 16 + gr;
                    a[mt][0] = *reinterpret_cast<const uint32_t*>(&As[buf][r0][ks + 2 * fc]);
                    a[mt][1] = *reinterpret_cast<const uint32_t*>(&As[buf][r0 + 8][ks + 2 * fc]);
                    a[mt][2] = *reinterpret_cast<const uint32_t*>(&As[buf][r0][ks + 2 * fc + 8]);
                    a[mt][3] = *reinterpret_cast<const uint32_t*>(&As[buf][r0 + 8][ks + 2 * fc + 8]);
                }
#pragma unroll
                for (int nt = 0; nt < 8; nt++) {
                    int bn = wn + nt * 8 + gr;
                    uint32_t b0 = *reinterpret_cast<const uint32_t*>(&Bs[buf][bn][ks + 2 * fc]);
                    uint32_t b1 = *reinterpret_cast<const uint32_t*>(&Bs[buf][bn][ks + 2 * fc + 8]);
                    mmah(acc[0][nt], a[0], b0, b1);
                    mmah(acc[1][nt], a[1], b0, b1);
                }
            }
            __syncthreads();
            buf ^= 1;
        }
    }

    // epilogue + fused stats
    float cs0[8], cs1[8], cq0[8], cq1[8];
#pragma unroll
    for (int nt = 0; nt < 8; nt++) { cs0[nt] = 0.f; cs1[nt] = 0.f; cq0[nt] = 0.f; cq1[nt] = 0.f; }
#pragma unroll
    for (int mt = 0; mt < 2; mt++) {
        int rbase = rowBase + wm + mt * 16 + gr;
#pragma unroll
        for (int ph = 0; ph < 2; ph++) {
            int rr = rbase + 8 * ph;
            if (rr < NN) {
                float dg = bias2 ? degf[rr] : 0.f;
#pragma unroll
                for (int nt = 0; nt < 8; nt++) {
                    int cc = colBase + wn + nt * 8 + 2 * fc;
                    float v0 = acc[mt][nt][2 * ph + 0] + bias1[cc];
                    float v1 = acc[mt][nt][2 * ph + 1] + bias1[cc + 1];
                    if (bias2) {
                        v0 = fmaf(dg, bias2[cc], v0);
                        v1 = fmaf(dg, bias2[cc + 1], v1);
                    }
                    if (addraw) {
                        float2 ar = *reinterpret_cast<const float2*>(addraw + (size_t)rr * HH + cc);
                        v0 = fmaf(ar.x, asc[cc], v0 + ash[cc]);
                        v1 = fmaf(ar.y, asc[cc + 1], v1 + ash[cc + 1]);
                    }
                    v0 = fmaxf(v0, 0.f);
                    v1 = fmaxf(v1, 0.f);
                    cs0[nt] += v0; cq0[nt] = fmaf(v0, v0, cq0[nt]);
                    cs1[nt] += v1; cq1[nt] = fmaf(v1, v1, cq1[nt]);
                    *reinterpret_cast<float2*>(C + (size_t)rr * HH + cc) = make_float2(v0, v1);
                    if (Chf) {
                        __half2 hp = __floats2half2_rn(v0, v1);
                        *reinterpret_cast<__half2*>(Chf + (size_t)rr * HH + cc) = hp;
                    }
                }
            }
        }
    }
    if (stout) {
#pragma unroll
        for (int nt = 0; nt < 8; nt++) {
#pragma unroll
            for (int off = 4; off < 32; off <<= 1) {
                cs0[nt] += __shfl_xor_sync(0xffffffffu, cs0[nt], off);
                cs1[nt] += __shfl_xor_sync(0xffffffffu, cs1[nt], off);
                cq0[nt] += __shfl_xor_sync(0xffffffffu, cq0[nt], off);
                cq1[nt] += __shfl_xor_sync(0xffffffffu, cq1[nt], off);
            }
            if (lane < 4) {
                int cc = colBase + wn + nt * 8 + 2 * lane;
                atomicAdd(&stout[cc], cs0[nt]);
                atomicAdd(&stout[cc + 1], cs1[nt]);
                atomicAdd(&stout[HH + cc], cq0[nt]);
                atomicAdd(&stout[HH + cc + 1], cq1[nt]);
            }
        }
    }
}

// ---------------- scsh / affine ----------------
__global__ void scsh_k(const float* __restrict__ st, const float* __restrict__ ga,
                       const float* __restrict__ be, float* __restrict__ sc,
                       float* __restrict__ sh) {
    int c = threadIdx.x;
    const float invN = 1.0f / (float)NN;
    float mu = st[c] * invN;
    float var = st[HH + c] * invN - mu * mu;
    float s = rsqrtf(var + BNEPS) * ga[c];
    sc[c] = s; sh[c] = be[c] - mu * s;
}
__global__ void affh_k(const float* __restrict__ X, hf* __restrict__ O,
                       const float* __restrict__ sc, const float* __restrict__ sh) {
    const int c = threadIdx.x;  // stride multiple of 256 keeps column fixed
    float s = sc[c], t = sh[c];
    size_t stride = (size_t)gridDim.x * blockDim.x;
    for (size_t i = (size_t)blockIdx.x * blockDim.x + threadIdx.x; i < (size_t)NN * HH; i += stride)
        O[i] = __float2half(fmaf(X[i], s, t));
}
__global__ void aff_k(const float* __restrict__ X, float* __restrict__ Y,
                      const float* __restrict__ sc, const float* __restrict__ sh) {
    const int c = threadIdx.x;
    float s = sc[c], t = sh[c];
    size_t stride = (size_t)gridDim.x * blockDim.x;
    for (size_t i = (size_t)blockIdx.x * blockDim.x + threadIdx.x; i < (size_t)NN * HH; i += stride)
        Y[i] = fmaf(X[i], s, t);
}

// ---------------- launcher ----------------
extern "C" void kernel_launch(void* const* d_in, const int* in_sizes, int n_in,
                              void* d_out, int out_size) {
    (void)in_sizes; (void)n_in; (void)out_size;
    const float* x = (const float*)d_in[0];
    const float* w = (const float*)d_in[1];
    const int* src = (const int*)d_in[2];
    const int* dst = (const int*)d_in[3];
    const float* aW = (const float*)d_in[4];
    const float* ab = (const float*)d_in[5];
    const float* bW0 = (const float*)d_in[6];
    const float* bb0 = (const float*)d_in[7];
    const float* gamma0 = (const float*)d_in[8];
    const float* beta0 = (const float*)d_in[9];
    const float* bondW = (const float*)d_in[10];
    const float* bondb = (const float*)d_in[11];
    const float* W1 = (const float*)d_in[12];
    const float* b1 = (const float*)d_in[13];
    const float* W2 = (const float*)d_in[14];
    const float* b2 = (const float*)d_in[15];
    const float* gamma1 = (const float*)d_in[16];
    const float* beta1 = (const float*)d_in[17];
    const float* gamma2 = (const float*)d_in[18];
    const float* beta2 = (const float*)d_in[19];

#define GSA(p, s) cudaGetSymbolAddress((void**)&p, s)
    float *pdeg, *pX, *pY, *pZ, *pst, *psc, *psh;
    hf *pXh, *pYh, *px16, *pws, *py16, *pz16, *paW, *pbW0, *pbond, *pW1, *pW2;
    GSA(pdeg, g_degf); GSA(pX, g_X); GSA(pY, g_Y); GSA(pZ, g_Z);
    GSA(pXh, g_Xh); GSA(pYh, g_Yh);
    GSA(pst, g_stats); GSA(psc, g_sc); GSA(psh, g_sh);
    GSA(px16, g_x16); GSA(pws, g_ws16); GSA(py16, g_y16); GSA(pz16, g_z16);
    GSA(paW, g_aWt); GSA(pbW0, g_bW0t); GSA(pbond, g_bondt);
    GSA(pW1, g_W1t); GSA(pW2, g_W2t);

    const int EB = (EE + 255) / 256, WB = (NN * 32 + 255) / 256;
    const dim3 gg(HH / 128, (NN + 127) / 128);  // (2, 391)

    init_k<<<256, 256>>>();
    hist_k<<<EB, 256>>>(dst);
    scan_k<<<1, 1024>>>();
    scatter_k<<<EB, 256>>>(src, dst);
    ws_k<<<WB, 256>>>(w);
    xc_k<<<(NN * AA + 255) / 256, 256>>>(x);
    wt_k<<<dim3((HH * AA + 255) / 256, 1), 256>>>(aW, AA, paW);
    wt_k<<<dim3((HH * BB + 255) / 256, 1), 256>>>(bW0, BB, pbW0);
    wt_k<<<dim3((HH * BB + 255) / 256, LL), 256>>>(bondW, BB, pbond);
    wt_k<<<dim3((HH * HH + 255) / 256, LL), 256>>>(W1, HH, pW1);
    wt_k<<<dim3((HH * HH + 255) / 256, LL), 256>>>(W2, HH, pW2);

    float* X = pX; float* Y = pY; float* Z = pZ;
    hf* Xh = pXh; hf* Yh = pYh;
    // ---- first layer: X (+fp16 copy) ----
    gemm_h<<<gg, 256>>>(px16, paW, AA, pws, pbW0, BB, ab, bb0, pdeg,
                        nullptr, nullptr, nullptr, pst, X, Xh);
    scsh_k<<<1, 256>>>(pst, gamma0, beta0, psc, psh);
    int pidx = 0;
    for (int l = 0; l < LL; l++) {
        int midx = 1 + 2 * l, oidx = 2 + 2 * l;
        const float* scp = psc + pidx * HH;
        const float* shp = psh + pidx * HH;
        spmm_k<<<WB, 256>>>(Xh, py16, scp, shp);
        gemm_h<<<gg, 256>>>(py16, pW1 + (size_t)l * HH * HH, HH,
                            pws, pbond + (size_t)l * HH * BB, BB,
                            b1 + l * HH, bondb + l * HH, pdeg,
                            nullptr, nullptr, nullptr,
                            pst + midx * 2 * HH, Z, nullptr);
        scsh_k<<<1, 256>>>(pst + midx * 2 * HH, gamma1 + l * HH, beta1 + l * HH,
                           psc + midx * HH, psh + midx * HH);
        affh_k<<<4096, 256>>>(Z, pz16, psc + midx * HH, psh + midx * HH);
        gemm_h<<<gg, 256>>>(pz16, pW2 + (size_t)l * HH * HH, HH,
                            nullptr, nullptr, 0,
                            b2 + l * HH, nullptr, nullptr,
                            X, scp, shp,
                            pst + oidx * 2 * HH, Y, (l + 1 < LL) ? Yh : nullptr);
        scsh_k<<<1, 256>>>(pst + oidx * 2 * HH, gamma2 + l * HH, beta2 + l * HH,
                           psc + oidx * HH, psh + oidx * HH);
        float* tmp = X; X = Y; Y = tmp;
        hf* tmph = Xh; Xh = Yh; Yh = tmph;
        pidx = oidx;
    }
    aff_k<<<4096, 256>>>(X, (float*)d_out, psc + pidx * HH, psh + pidx * HH);
}

// round 16
// speedup vs baseline: 2.5168x; 1.0105x over previous
#include <cuda_runtime.h>
#include <cuda_fp16.h>
#include <cstddef>
#include <cstdint>

#define NN 50000
#define EE 800000
#define HH 256
#define AA 128
#define BB 32
#define LL 3
#define BNEPS 1e-5f
#define NSTG 4
#define ASTRIDE 40
#define A_ST (128 * ASTRIDE)
#define SMEMB (NSTG * A_ST * 2 * 2)

typedef __half hf;

// ---------------- device scratch ----------------
__device__ int g_deg[NN];
__device__ int g_rowcur[NN];
__device__ int g_rowptr[NN + 1];
__device__ int g_colsrc[EE];
__device__ int g_eidx[EE];
__device__ __align__(16) float g_degf[NN];
__device__ __align__(16) float g_X[(size_t)NN * HH];
__device__ __align__(16) float g_Y[(size_t)NN * HH];
__device__ __align__(16) float g_Z[(size_t)NN * HH];
__device__ __align__(16) hf g_Xh[(size_t)NN * HH];
__device__ __align__(16) hf g_Yh[(size_t)NN * HH];
__device__ __align__(16) hf g_x16[(size_t)NN * AA];
__device__ __align__(16) hf g_ws16[(size_t)NN * BB];
__device__ __align__(16) hf g_y16[(size_t)NN * HH];
__device__ __align__(16) hf g_z16[(size_t)NN * HH];
__device__ __align__(16) hf g_aWt[HH * AA];
__device__ __align__(16) hf g_bW0t[HH * BB];
__device__ __align__(16) hf g_bondt[LL * HH * BB];
__device__ __align__(16) hf g_W1t[LL * HH * HH];
__device__ __align__(16) hf g_W2t[LL * HH * HH];
__device__ float g_stats[7 * 2 * HH];
__device__ float g_sc[7 * HH];
__device__ float g_sh[7 * HH];

// ---------------- helpers ----------------
__device__ __forceinline__ void cpa16(const hf* dst, const hf* src, bool ok) {
    uint32_t d = (uint32_t)__cvta_generic_to_shared(dst);
    int sz = ok ? 16 : 0;
    asm volatile("cp.async.ca.shared.global [%0], [%1], 16, %2;" :: "r"(d), "l"(src), "r"(sz));
}
__device__ __forceinline__ void mmah(float* d, const uint32_t* a, uint32_t b0, uint32_t b1) {
    asm volatile(
        "mma.sync.aligned.m16n8k16.row.col.f32.f16.f16.f32 "
        "{%0,%1,%2,%3}, {%4,%5,%6,%7}, {%8,%9}, {%0,%1,%2,%3};"
        : "+f"(d[0]), "+f"(d[1]), "+f"(d[2]), "+f"(d[3])
        : "r"(a[0]), "r"(a[1]), "r"(a[2]), "r"(a[3]), "r"(b0), "r"(b1));
}

// ---------------- setup ----------------
__global__ void init_k() {
    int i = blockIdx.x * blockDim.x + threadIdx.x, st = gridDim.x * blockDim.x;
    for (int t = i; t < NN; t += st) { g_deg[t] = 0; g_rowcur[t] = 0; }
    for (int t = i; t < 7 * 2 * HH; t += st) g_stats[t] = 0.f;
}
__global__ void hist_k(const int* __restrict__ dst) {
    int e = blockIdx.x * blockDim.x + threadIdx.x;
    if (e < EE) atomicAdd(&g_deg[dst[e]], 1);
}
__global__ void scan_k() {
    __shared__ int part[1024];
    const int t = threadIdx.x, CH = (NN + 1023) / 1024, base = t * CH;
    int s = 0;
    for (int i = 0; i < CH; i++) { int x = base + i; if (x < NN) s += g_deg[x]; }
    part[t] = s;
    __syncthreads();
    for (int off = 1; off < 1024; off <<= 1) {
        int v = (t >= off) ? part[t - off] : 0;
        __syncthreads(); part[t] += v; __syncthreads();
    }
    int run = (t == 0) ? 0 : part[t - 1];
    for (int i = 0; i < CH; i++) {
        int x = base + i;
        if (x < NN) { int d = g_deg[x]; g_rowptr[x] = run; g_degf[x] = (float)d; run += d; }
    }
    if (t == 1023) g_rowptr[NN] = part[1023];
}
__global__ void scatter_k(const int* __restrict__ src, const int* __restrict__ dst) {
    int e = blockIdx.x * blockDim.x + threadIdx.x;
    if (e < EE) {
        int d = dst[e];
        int p = g_rowptr[d] + atomicAdd(&g_rowcur[d], 1);
        g_colsrc[p] = src[e]; g_eidx[p] = e;
    }
}
__global__ void ws_k(const float* __restrict__ w) {
    int gw = (blockIdx.x * blockDim.x + threadIdx.x) >> 5, lane = threadIdx.x & 31;
    if (gw >= NN) return;
    int s = g_rowptr[gw], e = g_rowptr[gw + 1];
    float acc = 0.f;
    for (int j = s; j < e; j++) acc += __ldg(&w[(size_t)g_eidx[j] * BB + lane]);
    g_ws16[(size_t)gw * BB + lane] = __float2half(acc);
}
__global__ void xc_k(const float* __restrict__ x) {
    int i = blockIdx.x * blockDim.x + threadIdx.x;
    if (i < NN * AA) g_x16[i] = __float2half(x[i]);
}
__global__ void wt_k(const float* __restrict__ W, int K, hf* __restrict__ out) {
    int l = blockIdx.y;
    int i = blockIdx.x * blockDim.x + threadIdx.x;
    if (i >= HH * K) return;
    int n = i / K, k = i % K;
    out[(size_t)l * HH * K + i] = __float2half(W[(size_t)l * K * HH + (size_t)k * HH + n]);
}

// ---------------- SpMM (fp16 gather): O=half(sc*sum F16[src] + deg*sh) ----------------
__global__ void spmm_k(const hf* __restrict__ F, hf* __restrict__ O,
                       const float* __restrict__ sc, const float* __restrict__ sh) {
    int gw = (blockIdx.x * blockDim.x + threadIdx.x) >> 5, lane = threadIdx.x & 31;
    if (gw >= NN) return;
    int s = g_rowptr[gw], e = g_rowptr[gw + 1];
    float acc[8];
#pragma unroll
    for (int u = 0; u < 8; u++) acc[u] = 0.f;
    for (int j = s; j < e; j++) {
        const uint4* r = reinterpret_cast<const uint4*>(F + (size_t)g_colsrc[j] * HH);
        uint4 v = __ldg(&r[lane]);
        __half2 h0 = *reinterpret_cast<__half2*>(&v.x);
        __half2 h1 = *reinterpret_cast<__half2*>(&v.y);
        __half2 h2 = *reinterpret_cast<__half2*>(&v.z);
        __half2 h3 = *reinterpret_cast<__half2*>(&v.w);
        float2 f0 = __half22float2(h0), f1 = __half22float2(h1);
        float2 f2 = __half22float2(h2), f3 = __half22float2(h3);
        acc[0] += f0.x; acc[1] += f0.y; acc[2] += f1.x; acc[3] += f1.y;
        acc[4] += f2.x; acc[5] += f2.y; acc[6] += f3.x; acc[7] += f3.y;
    }
    float dg = (float)(e - s);
    int c0 = lane * 8;
    float4 sA = *reinterpret_cast<const float4*>(sc + c0);
    float4 sB = *reinterpret_cast<const float4*>(sc + c0 + 4);
    float4 tA = *reinterpret_cast<const float4*>(sh + c0);
    float4 tB = *reinterpret_cast<const float4*>(sh + c0 + 4);
    float o[8];
    o[0] = fmaf(acc[0], sA.x, dg * tA.x); o[1] = fmaf(acc[1], sA.y, dg * tA.y);
    o[2] = fmaf(acc[2], sA.z, dg * tA.z); o[3] = fmaf(acc[3], sA.w, dg * tA.w);
    o[4] = fmaf(acc[4], sB.x, dg * tB.x); o[5] = fmaf(acc[5], sB.y, dg * tB.y);
    o[6] = fmaf(acc[6], sB.z, dg * tB.z); o[7] = fmaf(acc[7], sB.w, dg * tB.w);
    uint4 w;
    __half2 p0 = __floats2half2_rn(o[0], o[1]), p1 = __floats2half2_rn(o[2], o[3]);
    __half2 p2 = __floats2half2_rn(o[4], o[5]), p3 = __floats2half2_rn(o[6], o[7]);
    w.x = *reinterpret_cast<uint32_t*>(&p0); w.y = *reinterpret_cast<uint32_t*>(&p1);
    w.z = *reinterpret_cast<uint32_t*>(&p2); w.w = *reinterpret_cast<uint32_t*>(&p3);
    reinterpret_cast<uint4*>(O + (size_t)gw * HH)[lane] = w;
}

// ---------------- fp16 GEMM: 4-stage cp.async pipeline over unified chunk stream ----------------
__global__ void __launch_bounds__(256, 2) gemm_h(
    const hf* __restrict__ A1, const hf* __restrict__ B1, int K1,
    const hf* __restrict__ A2, const hf* __restrict__ B2, int K2,
    const float* __restrict__ bias1, const float* __restrict__ bias2,
    const float* __restrict__ degf,
    const float* __restrict__ addraw, const float* __restrict__ asc,
    const float* __restrict__ ash,
    float* __restrict__ stout, float* __restrict__ C, hf* __restrict__ Chf)
{
    extern __shared__ hf smA[];
    hf* smB = smA + NSTG * A_ST;
    const int tid = threadIdx.x, lane = tid & 31, warp = tid >> 5;
    const int wm = (warp & 3) * 32, wn = (warp >> 2) * 64;
    const int rowBase = blockIdx.y * 128, colBase = blockIdx.x * 128;
    const int gr = lane >> 2, fc = lane & 3;

    float acc[2][8][4];
#pragma unroll
    for (int mt = 0; mt < 2; mt++)
#pragma unroll
        for (int nt = 0; nt < 8; nt++)
#pragma unroll
            for (int q = 0; q < 4; q++) acc[mt][nt][q] = 0.f;

    const int nc1 = K1 >> 5;
    const int T = nc1 + (A2 ? (K2 >> 5) : 0);

    auto ldchunk = [&](int c) {
        int stg = c & (NSTG - 1);
        const hf* Ap; const hf* Bp; int K, k0;
        if (c < nc1) { Ap = A1; Bp = B1; K = K1; k0 = c * 32; }
        else { Ap = A2; Bp = B2; K = K2; k0 = (c - nc1) * 32; }
        hf* Ad = smA + stg * A_ST;
        hf* Bd = smB + stg * A_ST;
#pragma unroll
        for (int i = 0; i < 2; i++) {
            int ch = i * 256 + tid, m = ch >> 2, c4 = ch & 3;
            int gm = rowBase + m;
            bool ok = gm < NN;
            cpa16(Ad + m * ASTRIDE + c4 * 8, Ap + (size_t)(ok ? gm : 0) * K + k0 + c4 * 8, ok);
            cpa16(Bd + m * ASTRIDE + c4 * 8, Bp + (size_t)(colBase + m) * K + k0 + c4 * 8, true);
        }
        asm volatile("cp.async.commit_group;" ::: "memory");
    };

    // prologue: stages 0..2 (T >= 5 for every call site)
    ldchunk(0); ldchunk(1); ldchunk(2);

#pragma unroll 1
    for (int it = 0; it < T; it++) {
        if (it + 3 < T) ldchunk(it + 3);
        else asm volatile("cp.async.commit_group;" ::: "memory");
        asm volatile("cp.async.wait_group 3;" ::: "memory");
        __syncthreads();
        const hf* Aa = smA + (it & (NSTG - 1)) * A_ST;
        const hf* Bb = smB + (it & (NSTG - 1)) * A_ST;
#pragma unroll
        for (int ks = 0; ks < 32; ks += 16) {
            uint32_t a[2][4];
#pragma unroll
            for (int mt = 0; mt < 2; mt++) {
                int r0 = wm + mt * 16 + gr;
                a[mt][0] = *reinterpret_cast<const uint32_t*>(&Aa[r0 * ASTRIDE + ks + 2 * fc]);
                a[mt][1] = *reinterpret_cast<const uint32_t*>(&Aa[(r0 + 8) * ASTRIDE + ks + 2 * fc]);
                a[mt][2] = *reinterpret_cast<const uint32_t*>(&Aa[r0 * ASTRIDE + ks + 2 * fc + 8]);
                a[mt][3] = *reinterpret_cast<const uint32_t*>(&Aa[(r0 + 8) * ASTRIDE + ks + 2 * fc + 8]);
            }
#pragma unroll
            for (int nt = 0; nt < 8; nt++) {
                int bn = wn + nt * 8 + gr;
                uint32_t b0 = *reinterpret_cast<const uint32_t*>(&Bb[bn * ASTRIDE + ks + 2 * fc]);
                uint32_t b1 = *reinterpret_cast<const uint32_t*>(&Bb[bn * ASTRIDE + ks + 2 * fc + 8]);
                mmah(acc[0][nt], a[0], b0, b1);
                mmah(acc[1][nt], a[1], b0, b1);
            }
        }
        __syncthreads();
    }

    // epilogue + fused stats
    float cs0[8], cs1[8], cq0[8], cq1[8];
#pragma unroll
    for (int nt = 0; nt < 8; nt++) { cs0[nt] = 0.f; cs1[nt] = 0.f; cq0[nt] = 0.f; cq1[nt] = 0.f; }
#pragma unroll
    for (int mt = 0; mt < 2; mt++) {
        int rbase = rowBase + wm + mt * 16 + gr;
#pragma unroll
        for (int ph = 0; ph < 2; ph++) {
            int rr = rbase + 8 * ph;
            if (rr < NN) {
                float dg = bias2 ? degf[rr] : 0.f;
#pragma unroll
                for (int nt = 0; nt < 8; nt++) {
                    int cc = colBase + wn + nt * 8 + 2 * fc;
                    float v0 = acc[mt][nt][2 * ph + 0] + bias1[cc];
                    float v1 = acc[mt][nt][2 * ph + 1] + bias1[cc + 1];
                    if (bias2) {
                        v0 = fmaf(dg, bias2[cc], v0);
                        v1 = fmaf(dg, bias2[cc + 1], v1);
                    }
                    if (addraw) {
                        float2 ar = *reinterpret_cast<const float2*>(addraw + (size_t)rr * HH + cc);
                        v0 = fmaf(ar.x, asc[cc], v0 + ash[cc]);
                        v1 = fmaf(ar.y, asc[cc + 1], v1 + ash[cc + 1]);
                    }
                    v0 = fmaxf(v0, 0.f);
                    v1 = fmaxf(v1, 0.f);
                    cs0[nt] += v0; cq0[nt] = fmaf(v0, v0, cq0[nt]);
                    cs1[nt] += v1; cq1[nt] = fmaf(v1, v1, cq1[nt]);
                    *reinterpret_cast<float2*>(C + (size_t)rr * HH + cc) = make_float2(v0, v1);
                    if (Chf) {
                        __half2 hp = __floats2half2_rn(v0, v1);
                        *reinterpret_cast<__half2*>(Chf + (size_t)rr * HH + cc) = hp;
                    }
                }
            }
        }
    }
    if (stout) {
#pragma unroll
        for (int nt = 0; nt < 8; nt++) {
#pragma unroll
            for (int off = 4; off < 32; off <<= 1) {
                cs0[nt] += __shfl_xor_sync(0xffffffffu, cs0[nt], off);
                cs1[nt] += __shfl_xor_sync(0xffffffffu, cs1[nt], off);
                cq0[nt] += __shfl_xor_sync(0xffffffffu, cq0[nt], off);
                cq1[nt] += __shfl_xor_sync(0xffffffffu, cq1[nt], off);
            }
            if (lane < 4) {
                int cc = colBase + wn + nt * 8 + 2 * lane;
                atomicAdd(&stout[cc], cs0[nt]);
                atomicAdd(&stout[cc + 1], cs1[nt]);
                atomicAdd(&stout[HH + cc], cq0[nt]);
                atomicAdd(&stout[HH + cc + 1], cq1[nt]);
            }
        }
    }
}

// ---------------- scsh / affine ----------------
__global__ void scsh_k(const float* __restrict__ st, const float* __restrict__ ga,
                       const float* __restrict__ be, float* __restrict__ sc,
                       float* __restrict__ sh) {
    int c = threadIdx.x;
    const float invN = 1.0f / (float)NN;
    float mu = st[c] * invN;
    float var = st[HH + c] * invN - mu * mu;
    float s = rsqrtf(var + BNEPS) * ga[c];
    sc[c] = s; sh[c] = be[c] - mu * s;
}
__global__ void affh_k(const float* __restrict__ X, hf* __restrict__ O,
                       const float* __restrict__ sc, const float* __restrict__ sh) {
    const int c = threadIdx.x;
    float s = sc[c], t = sh[c];
    size_t stride = (size_t)gridDim.x * blockDim.x;
    for (size_t i = (size_t)blockIdx.x * blockDim.x + threadIdx.x; i < (size_t)NN * HH; i += stride)
        O[i] = __float2half(fmaf(X[i], s, t));
}
__global__ void aff_k(const float* __restrict__ X, float* __restrict__ Y,
                      const float* __restrict__ sc, const float* __restrict__ sh) {
    const int c = threadIdx.x;
    float s = sc[c], t = sh[c];
    size_t stride = (size_t)gridDim.x * blockDim.x;
    for (size_t i = (size_t)blockIdx.x * blockDim.x + threadIdx.x; i < (size_t)NN * HH; i += stride)
        Y[i] = fmaf(X[i], s, t);
}

// ---------------- launcher ----------------
extern "C" void kernel_launch(void* const* d_in, const int* in_sizes, int n_in,
                              void* d_out, int out_size) {
    (void)in_sizes; (void)n_in; (void)out_size;
    const float* x = (const float*)d_in[0];
    const float* w = (const float*)d_in[1];
    const int* src = (const int*)d_in[2];
    const int* dst = (const int*)d_in[3];
    const float* aW = (const float*)d_in[4];
    const float* ab = (const float*)d_in[5];
    const float* bW0 = (const float*)d_in[6];
    const float* bb0 = (const float*)d_in[7];
    const float* gamma0 = (const float*)d_in[8];
    const float* beta0 = (const float*)d_in[9];
    const float* bondW = (const float*)d_in[10];
    const float* bondb = (const float*)d_in[11];
    const float* W1 = (const float*)d_in[12];
    const float* b1 = (const float*)d_in[13];
    const float* W2 = (const float*)d_in[14];
    const float* b2 = (const float*)d_in[15];
    const float* gamma1 = (const float*)d_in[16];
    const float* beta1 = (const float*)d_in[17];
    const float* gamma2 = (const float*)d_in[18];
    const float* beta2 = (const float*)d_in[19];

#define GSA(p, s) cudaGetSymbolAddress((void**)&p, s)
    float *pdeg, *pX, *pY, *pZ, *pst, *psc, *psh;
    hf *pXh, *pYh, *px16, *pws, *py16, *pz16, *paW, *pbW0, *pbond, *pW1, *pW2;
    GSA(pdeg, g_degf); GSA(pX, g_X); GSA(pY, g_Y); GSA(pZ, g_Z);
    GSA(pXh, g_Xh); GSA(pYh, g_Yh);
    GSA(pst, g_stats); GSA(psc, g_sc); GSA(psh, g_sh);
    GSA(px16, g_x16); GSA(pws, g_ws16); GSA(py16, g_y16); GSA(pz16, g_z16);
    GSA(paW, g_aWt); GSA(pbW0, g_bW0t); GSA(pbond, g_bondt);
    GSA(pW1, g_W1t); GSA(pW2, g_W2t);

    const int EB = (EE + 255) / 256, WB = (NN * 32 + 255) / 256;
    const dim3 gg(HH / 128, (NN + 127) / 128);  // (2, 391)

    cudaFuncSetAttribute(gemm_h, cudaFuncAttributeMaxDynamicSharedMemorySize, SMEMB);

    init_k<<<256, 256>>>();
    hist_k<<<EB, 256>>>(dst);
    scan_k<<<1, 1024>>>();
    scatter_k<<<EB, 256>>>(src, dst);
    ws_k<<<WB, 256>>>(w);
    xc_k<<<(NN * AA + 255) / 256, 256>>>(x);
    wt_k<<<dim3((HH * AA + 255) / 256, 1), 256>>>(aW, AA, paW);
    wt_k<<<dim3((HH * BB + 255) / 256, 1), 256>>>(bW0, BB, pbW0);
    wt_k<<<dim3((HH * BB + 255) / 256, LL), 256>>>(bondW, BB, pbond);
    wt_k<<<dim3((HH * HH + 255) / 256, LL), 256>>>(W1, HH, pW1);
    wt_k<<<dim3((HH * HH + 255) / 256, LL), 256>>>(W2, HH, pW2);

    float* X = pX; float* Y = pY; float* Z = pZ;
    hf* Xh = pXh; hf* Yh = pYh;
    // ---- first layer: X (+fp16 copy) ----
    gemm_h<<<gg, 256, SMEMB>>>(px16, paW, AA, pws, pbW0, BB, ab, bb0, pdeg,
                               nullptr, nullptr, nullptr, pst, X, Xh);
    scsh_k<<<1, 256>>>(pst, gamma0, beta0, psc, psh);
    int pidx = 0;
    for (int l = 0; l < LL; l++) {
        int midx = 1 + 2 * l, oidx = 2 + 2 * l;
        const float* scp = psc + pidx * HH;
        const float* shp = psh + pidx * HH;
        spmm_k<<<WB, 256>>>(Xh, py16, scp, shp);
        gemm_h<<<gg, 256, SMEMB>>>(py16, pW1 + (size_t)l * HH * HH, HH,
                                   pws, pbond + (size_t)l * HH * BB, BB,
                                   b1 + l * HH, bondb + l * HH, pdeg,
                                   nullptr, nullptr, nullptr,
                                   pst + midx * 2 * HH, Z, nullptr);
        scsh_k<<<1, 256>>>(pst + midx * 2 * HH, gamma1 + l * HH, beta1 + l * HH,
                           psc + midx * HH, psh + midx * HH);
        affh_k<<<4096, 256>>>(Z, pz16, psc + midx * HH, psh + midx * HH);
        gemm_h<<<gg, 256, SMEMB>>>(pz16, pW2 + (size_t)l * HH * HH, HH,
                                   nullptr, nullptr, 0,
                                   b2 + l * HH, nullptr, nullptr,
                                   X, scp, shp,
                                   pst + oidx * 2 * HH, Y, (l + 1 < LL) ? Yh : nullptr);
        scsh_k<<<1, 256>>>(pst + oidx * 2 * HH, gamma2 + l * HH, beta2 + l * HH,
                           psc + oidx * HH, psh + oidx * HH);
        float* tmp = X; X = Y; Y = tmp;
        hf* tmph = Xh; Xh = Yh; Yh = tmph;
        pidx = oidx;
    }
    aff_k<<<4096, 256>>>(X, (float*)d_out, psc + pidx * HH, psh + pidx * HH);
}